// round 1
// baseline (speedup 1.0000x reference)
#include <cuda_runtime.h>
#include <math.h>

#define H 1024
#define F 4096
#define E 8
#define T 2048
#define SLOTS (2*T)

#define BM 128
#define BN 64
#define BK 32

// ---- device-global scratch (no allocations allowed) ----
__device__ int   g_count[E];
__device__ int   g_list[E][T];        // slot ids (t*2 + k) grouped per expert
__device__ float g_wslot[SLOTS];      // renormalized gate weight per slot
__device__ float g_hmid[(size_t)SLOTS * F];    // 64 MB: silu(xW1)*(xW3)
__device__ float g_outpair[(size_t)SLOTS * H]; // 16 MB: per-slot down-proj output

__global__ void zero_counts_kernel() {
    if (threadIdx.x < E) g_count[threadIdx.x] = 0;
}

// ---- router: logits -> top2 -> renorm weights -> per-expert scatter ----
__global__ __launch_bounds__(256) void router_kernel(
    const float* __restrict__ x, const float* __restrict__ Wr)
{
    int t = blockIdx.x;
    __shared__ float xs[H];
    __shared__ float logits[E];
    int tid = threadIdx.x;
    for (int i = tid; i < H; i += 256) xs[i] = x[(size_t)t * H + i];
    __syncthreads();

    int w = tid >> 5, lane = tid & 31;   // exactly 8 warps: warp w -> expert w
    {
        const float* wr = Wr + w * H;
        float s = 0.f;
        for (int i = lane; i < H; i += 32) s += xs[i] * wr[i];
        #pragma unroll
        for (int off = 16; off; off >>= 1) s += __shfl_xor_sync(0xffffffffu, s, off);
        if (lane == 0) logits[w] = s;
    }
    __syncthreads();

    if (tid == 0) {
        // top-1, first occurrence on ties (matches jax top_k)
        int e0 = 0; float b0 = logits[0];
        #pragma unroll
        for (int e = 1; e < E; e++) if (logits[e] > b0) { b0 = logits[e]; e0 = e; }
        int e1 = -1; float b1 = -3.0e38f;
        #pragma unroll
        for (int e = 0; e < E; e++) if (e != e0 && logits[e] > b1) { b1 = logits[e]; e1 = e; }
        // renormalized top-2 softmax weights: w0 = exp(l0)/(exp(l0)+exp(l1))
        float w0 = 1.f / (1.f + expf(b1 - b0));
        float w1 = 1.f - w0;
        int p0 = atomicAdd(&g_count[e0], 1);
        int p1 = atomicAdd(&g_count[e1], 1);
        g_list[e0][p0] = 2 * t;
        g_list[e1][p1] = 2 * t + 1;
        g_wslot[2 * t]     = w0;
        g_wslot[2 * t + 1] = w1;
    }
}

// ---- GEMM1: per expert, gathered X[cnt,H] @ W1/W3[H,F] -> silu*up -> hmid ----
// block tile 128x64, thread tile 8x4 (dual accumulator)
__global__ __launch_bounds__(256) void expert_up_kernel(
    const float* __restrict__ x,
    const float* __restrict__ W1,
    const float* __restrict__ W3)
{
    int e   = blockIdx.z;
    int cnt = g_count[e];
    int m0  = blockIdx.y * BM;
    if (m0 >= cnt) return;
    int n0  = blockIdx.x * BN;

    __shared__ float Xs[BM][BK + 1];
    __shared__ float B1s[BK][BN];
    __shared__ float B3s[BK][BN];
    __shared__ int   stok[BM];
    __shared__ int   sslot[BM];

    int tid = threadIdx.x;
    for (int i = tid; i < BM; i += 256) {
        int r = m0 + i;
        int slot = (r < cnt) ? g_list[e][r] : -1;
        sslot[i] = slot;
        stok[i]  = (slot >= 0) ? (slot >> 1) : -1;
    }
    __syncthreads();

    int tx = tid & 15, ty = tid >> 4;  // tx: 16 n-groups, ty: 16 m-groups

    float acc1[8][4], acc3[8][4];
    #pragma unroll
    for (int i = 0; i < 8; i++)
        #pragma unroll
        for (int j = 0; j < 4; j++) { acc1[i][j] = 0.f; acc3[i][j] = 0.f; }

    const float* w1p = W1 + (size_t)e * H * F;
    const float* w3p = W3 + (size_t)e * H * F;

    for (int k0 = 0; k0 < H; k0 += BK) {
        for (int i = tid; i < BM * BK; i += 256) {
            int m = i >> 5, k = i & 31;
            int tok = stok[m];
            Xs[m][k] = (tok >= 0) ? x[(size_t)tok * H + k0 + k] : 0.f;
        }
        for (int i = tid; i < BK * BN; i += 256) {
            int k = i >> 6, n = i & 63;
            size_t off = (size_t)(k0 + k) * F + n0 + n;
            B1s[k][n] = w1p[off];
            B3s[k][n] = w3p[off];
        }
        __syncthreads();

        #pragma unroll
        for (int kk = 0; kk < BK; kk++) {
            float a[8], b1[4], b3[4];
            #pragma unroll
            for (int i = 0; i < 8; i++) a[i] = Xs[ty + 16 * i][kk];
            #pragma unroll
            for (int j = 0; j < 4; j++) { b1[j] = B1s[kk][tx + 16 * j]; b3[j] = B3s[kk][tx + 16 * j]; }
            #pragma unroll
            for (int i = 0; i < 8; i++)
                #pragma unroll
                for (int j = 0; j < 4; j++) {
                    acc1[i][j] += a[i] * b1[j];
                    acc3[i][j] += a[i] * b3[j];
                }
        }
        __syncthreads();
    }

    #pragma unroll
    for (int i = 0; i < 8; i++) {
        int m = ty + 16 * i;
        int slot = sslot[m];
        if (slot < 0) continue;
        float* dst = g_hmid + (size_t)slot * F + n0;
        #pragma unroll
        for (int j = 0; j < 4; j++) {
            float g = acc1[i][j];
            float u = acc3[i][j];
            float s = g / (1.f + expf(-g));  // silu
            dst[tx + 16 * j] = s * u;
        }
    }
}

// ---- GEMM2: per expert, hmid[cnt,F] @ W2[F,H], scaled by gate weight ----
__global__ __launch_bounds__(256) void expert_down_kernel(
    const float* __restrict__ W2)
{
    int e   = blockIdx.z;
    int cnt = g_count[e];
    int m0  = blockIdx.y * BM;
    if (m0 >= cnt) return;
    int n0  = blockIdx.x * BN;

    __shared__ float As[BM][BK + 1];
    __shared__ float Bs[BK][BN];
    __shared__ int   sslot[BM];

    int tid = threadIdx.x;
    for (int i = tid; i < BM; i += 256) {
        int r = m0 + i;
        sslot[i] = (r < cnt) ? g_list[e][r] : -1;
    }
    __syncthreads();

    int tx = tid & 15, ty = tid >> 4;

    float acc[8][4];
    #pragma unroll
    for (int i = 0; i < 8; i++)
        #pragma unroll
        for (int j = 0; j < 4; j++) acc[i][j] = 0.f;

    const float* w2p = W2 + (size_t)e * F * H;

    for (int k0 = 0; k0 < F; k0 += BK) {
        for (int i = tid; i < BM * BK; i += 256) {
            int m = i >> 5, k = i & 31;
            int slot = sslot[m];
            As[m][k] = (slot >= 0) ? g_hmid[(size_t)slot * F + k0 + k] : 0.f;
        }
        for (int i = tid; i < BK * BN; i += 256) {
            int k = i >> 6, n = i & 63;
            Bs[k][n] = w2p[(size_t)(k0 + k) * H + n0 + n];
        }
        __syncthreads();

        #pragma unroll
        for (int kk = 0; kk < BK; kk++) {
            float a[8], b[4];
            #pragma unroll
            for (int i = 0; i < 8; i++) a[i] = As[ty + 16 * i][kk];
            #pragma unroll
            for (int j = 0; j < 4; j++) b[j] = Bs[kk][tx + 16 * j];
            #pragma unroll
            for (int i = 0; i < 8; i++)
                #pragma unroll
                for (int j = 0; j < 4; j++) acc[i][j] += a[i] * b[j];
        }
        __syncthreads();
    }

    #pragma unroll
    for (int i = 0; i < 8; i++) {
        int m = ty + 16 * i;
        int slot = sslot[m];
        if (slot < 0) continue;
        float gw = g_wslot[slot];
        float* dst = g_outpair + (size_t)slot * H + n0;
        #pragma unroll
        for (int j = 0; j < 4; j++) dst[tx + 16 * j] = gw * acc[i][j];
    }
}

// ---- combine: out[t] = outpair[2t] + outpair[2t+1] (deterministic, no atomics) ----
__global__ __launch_bounds__(256) void combine_kernel(float* __restrict__ out)
{
    int i = blockIdx.x * 256 + threadIdx.x;
    if (i >= T * H) return;
    int t = i >> 10;       // /H
    int h = i & (H - 1);   // %H
    out[i] = g_outpair[(size_t)(2 * t) * H + h] + g_outpair[(size_t)(2 * t + 1) * H + h];
}

extern "C" void kernel_launch(void* const* d_in, const int* in_sizes, int n_in,
                              void* d_out, int out_size)
{
    const float* x  = (const float*)d_in[0];  // [T, H]
    const float* Wr = (const float*)d_in[1];  // [E, H]
    const float* W1 = (const float*)d_in[2];  // [E, H, F]
    const float* W2 = (const float*)d_in[3];  // [E, F, H]
    const float* W3 = (const float*)d_in[4];  // [E, H, F]
    float* out = (float*)d_out;               // [T, H]

    zero_counts_kernel<<<1, 32>>>();
    router_kernel<<<T, 256>>>(x, Wr);

    dim3 g1(F / BN, (T + BM - 1) / BM, E);
    expert_up_kernel<<<g1, 256>>>(x, W1, W3);

    dim3 g2(H / BN, (T + BM - 1) / BM, E);
    expert_down_kernel<<<g2, 256>>>(W2);

    combine_kernel<<<(T * H + 255) / 256, 256>>>(out);
}

// round 4
// speedup vs baseline: 1.4541x; 1.4541x over previous
#include <cuda_runtime.h>
#include <cuda_bf16.h>
#include <cstdint>
#include <math.h>

#define H 1024
#define F 4096
#define E 8
#define T 2048
#define SLOTS (2*T)

#define BM 128
#define BN 64
#define BK 64              // bf16 elements per K-chunk (128 bytes = SW128 atom row)
#define NC1 (H/BK)         // 16
#define NC2 (F/BK)         // 64
#define MT_MAX (T/BM)      // 16

#if defined(__CUDA_ARCH_FEAT_SM103_ALL) || defined(__CUDA_ARCH_FEAT_SM100_ALL) || \
    (defined(__CUDA_ARCH_SPECIFIC__) && (__CUDA_ARCH_SPECIFIC__ == 1030)) || \
    (defined(__CUDA_ARCH_FAMILY_SPECIFIC__) && (__CUDA_ARCH_FAMILY_SPECIFIC__ == 1030))
#define HAS_TCGEN05 1
#else
#define HAS_TCGEN05 0
#endif

__device__ int   g_count[E];
__device__ int   g_list[E][T];
__device__ float g_wslot[SLOTS];
__device__ float g_hmid[(size_t)SLOTS * F];
__device__ float g_outpair[(size_t)SLOTS * H];

__device__ __forceinline__ uint32_t smem_u32(const void* p) {
    uint32_t a;
    asm("{ .reg .u64 t; cvta.to.shared.u64 t, %1; cvt.u32.u64 %0, t; }" : "=r"(a) : "l"(p));
    return a;
}
__device__ __forceinline__ uint32_t swz128(uint32_t o) { return o ^ ((o >> 3) & 0x70); }

// split a float into bf16 hi + bf16 lo (A ≈ hi + lo)
__device__ __forceinline__ void bf16_split(float v, uint16_t& hi, uint16_t& lo) {
    __nv_bfloat16 h = __float2bfloat16(v);
    __nv_bfloat16 l = __float2bfloat16(v - __bfloat162float(h));
    hi = __bfloat16_as_ushort(h);
    lo = __bfloat16_as_ushort(l);
}

#if HAS_TCGEN05
static __device__ __forceinline__ uint64_t make_desc(uint32_t addr) {
    const uint64_t base = (uint64_t(2) << 61) | (uint64_t(1) << 46) |
                          (uint64_t(64) << 32) | (uint64_t(1) << 16);
    return base | ((uint64_t)(addr >> 4) & 0x3FFF);
}

// kind::f16 idesc: dtype F32(1)@4, atype BF16(1)@7, btype BF16(1)@10, N/8@17, M/16@24
#define IDESC_BF16 ((1u << 4) | (1u << 7) | (1u << 10) | ((BN / 8) << 17) | ((BM / 16) << 24))

__device__ __forceinline__ void mma_bf16_ss(uint32_t d, uint64_t ad, uint64_t bd, uint32_t en) {
    asm volatile(
        "{\n\t.reg .pred p;\n\t"
        "setp.ne.u32 p, %4, 0;\n\t"
        "tcgen05.mma.cta_group::1.kind::f16 [%0], %1, %2, %3, {%5,%5,%5,%5}, p;\n\t}"
        :: "r"(d), "l"(ad), "l"(bd), "r"(IDESC_BF16), "r"(en), "r"(0u) : "memory");
}
__device__ __forceinline__ void tmem_alloc(uint32_t smem_dst, uint32_t ncols) {
    asm volatile("tcgen05.alloc.cta_group::1.sync.aligned.shared::cta.b32 [%0], %1;"
                 :: "r"(smem_dst), "r"(ncols) : "memory");
}
__device__ __forceinline__ void tmem_dealloc(uint32_t tb, uint32_t ncols) {
    asm volatile("tcgen05.relinquish_alloc_permit.cta_group::1.sync.aligned;");
    asm volatile("tcgen05.dealloc.cta_group::1.sync.aligned.b32 %0, %1;" :: "r"(tb), "r"(ncols));
}
__device__ __forceinline__ void mma_commit(uint32_t mbar) {
    asm volatile("tcgen05.commit.cta_group::1.mbarrier::arrive::one.shared::cluster.b64 [%0];"
                 :: "r"(mbar) : "memory");
}
__device__ __forceinline__ void mbar_init(uint32_t mbar, uint32_t cnt) {
    asm volatile("mbarrier.init.shared.b64 [%0], %1;" :: "r"(mbar), "r"(cnt) : "memory");
}
__device__ __forceinline__ void mbar_wait(uint32_t mbar, uint32_t parity) {
    uint32_t done;
    asm volatile(
        "{\n\t.reg .pred p;\n\t"
        "mbarrier.try_wait.parity.acquire.cta.shared::cta.b64 p, [%1], %2;\n\t"
        "selp.b32 %0, 1, 0, p;\n\t}"
        : "=r"(done) : "r"(mbar), "r"(parity) : "memory");
    if (!done) {
        asm volatile(
            "{\n\t.reg .pred P1;\n\t"
            "W_%=:\n\t"
            "mbarrier.try_wait.parity.acquire.cta.shared::cta.b64 P1, [%0], %1, 0x989680;\n\t"
            "@P1 bra.uni D_%=;\n\t"
            "bra.uni W_%=;\n\t"
            "D_%=:\n\t}"
            :: "r"(mbar), "r"(parity) : "memory");
    }
}
__device__ __forceinline__ void fence_async_shared() {
    asm volatile("fence.proxy.async.shared::cta;" ::: "memory");
}
__device__ __forceinline__ void fence_tc_after() {
    asm volatile("tcgen05.fence::after_thread_sync;" ::: "memory");
}
__device__ __forceinline__ void ldtm_x32(uint32_t* r, uint32_t a) {
    asm volatile(
        "tcgen05.ld.sync.aligned.32x32b.x32.b32 "
        "{%0,%1,%2,%3,%4,%5,%6,%7,%8,%9,%10,%11,%12,%13,%14,%15,"
        "%16,%17,%18,%19,%20,%21,%22,%23,%24,%25,%26,%27,%28,%29,%30,%31}, [%32];"
        : "=r"(r[0]), "=r"(r[1]), "=r"(r[2]), "=r"(r[3]), "=r"(r[4]), "=r"(r[5]),
          "=r"(r[6]), "=r"(r[7]), "=r"(r[8]), "=r"(r[9]), "=r"(r[10]), "=r"(r[11]),
          "=r"(r[12]), "=r"(r[13]), "=r"(r[14]), "=r"(r[15]), "=r"(r[16]), "=r"(r[17]),
          "=r"(r[18]), "=r"(r[19]), "=r"(r[20]), "=r"(r[21]), "=r"(r[22]), "=r"(r[23]),
          "=r"(r[24]), "=r"(r[25]), "=r"(r[26]), "=r"(r[27]), "=r"(r[28]), "=r"(r[29]),
          "=r"(r[30]), "=r"(r[31])
        : "r"(a));
}
__device__ __forceinline__ void tmem_wait_ld() {
    asm volatile("tcgen05.wait::ld.sync.aligned;" ::: "memory");
}
#endif // HAS_TCGEN05

__global__ void zero_counts_kernel() {
    if (threadIdx.x < E) g_count[threadIdx.x] = 0;
}

__global__ __launch_bounds__(256) void router_kernel(
    const float* __restrict__ x, const float* __restrict__ Wr)
{
    int t = blockIdx.x;
    __shared__ float xs[H];
    __shared__ float logits[E];
    int tid = threadIdx.x;
    for (int i = tid; i < H; i += 256) xs[i] = x[(size_t)t * H + i];
    __syncthreads();
    int w = tid >> 5, lane = tid & 31;
    {
        const float* wr = Wr + w * H;
        float s = 0.f;
        for (int i = lane; i < H; i += 32) s += xs[i] * wr[i];
        #pragma unroll
        for (int off = 16; off; off >>= 1) s += __shfl_xor_sync(0xffffffffu, s, off);
        if (lane == 0) logits[w] = s;
    }
    __syncthreads();
    if (tid == 0) {
        int e0 = 0; float b0 = logits[0];
        #pragma unroll
        for (int e = 1; e < E; e++) if (logits[e] > b0) { b0 = logits[e]; e0 = e; }
        int e1 = -1; float b1 = -3.0e38f;
        #pragma unroll
        for (int e = 0; e < E; e++) if (e != e0 && logits[e] > b1) { b1 = logits[e]; e1 = e; }
        float w0 = 1.f / (1.f + expf(b1 - b0));
        float w1 = 1.f - w0;
        int p0 = atomicAdd(&g_count[e0], 1);
        int p1 = atomicAdd(&g_count[e1], 1);
        g_list[e0][p0] = 2 * t;
        g_list[e1][p1] = 2 * t + 1;
        g_wslot[2 * t]     = w0;
        g_wslot[2 * t + 1] = w1;
    }
}

// SMEM layouts (all tile bases 1024-aligned). A tile: 128x64 bf16 = 16KB.
// B tile: 64x64 bf16 = 8KB. 2 stages each.
#define G1_OFF_TMEM 0
#define G1_OFF_MBAR 16
#define G1_OFF_SLOT 64
#define G1_OFF_AH   1024
#define G1_OFF_AL   (G1_OFF_AH  + 2*16384)
#define G1_OFF_B1H  (G1_OFF_AL  + 2*16384)
#define G1_OFF_B1L  (G1_OFF_B1H + 2*8192)
#define G1_OFF_B3H  (G1_OFF_B1L + 2*8192)
#define G1_OFF_B3L  (G1_OFF_B3H + 2*8192)
#define G1_SMEM     (G1_OFF_B3L + 2*8192)

__global__ __launch_bounds__(256) void expert_up_mma(
    const float* __restrict__ x,
    const float* __restrict__ W1,
    const float* __restrict__ W3)
{
#if HAS_TCGEN05
    extern __shared__ char smem[];
    int e   = blockIdx.z;
    int cnt = g_count[e];
    int m0  = blockIdx.y * BM;
    if (m0 >= cnt) return;
    int n0  = blockIdx.x * BN;

    uint32_t sb = smem_u32(smem);
    int tid = threadIdx.x, wid = tid >> 5, lane = tid & 31;
    int* sslot = (int*)(smem + G1_OFF_SLOT);
    if (tid < BM) { int r = m0 + tid; sslot[tid] = (r < cnt) ? g_list[e][r] : -1; }
    if (tid == 0) { mbar_init(sb + G1_OFF_MBAR, 1); mbar_init(sb + G1_OFF_MBAR + 8, 1); }
    if (wid == 0) tmem_alloc(sb + G1_OFF_TMEM, 128);
    __syncthreads();
    uint32_t tb;
    asm volatile("ld.shared.b32 %0, [%1];" : "=r"(tb) : "r"(sb + G1_OFF_TMEM));

    const float* w1p = W1 + (size_t)e * H * F;
    const float* w3p = W3 + (size_t)e * H * F;

    int ph0 = 0, ph1 = 0;
    for (int kc = 0; kc < NC1; kc++) {
        int s = kc & 1;
        int k0 = kc * BK;
        if (kc >= 2) {
            if (s == 0) { mbar_wait(sb + G1_OFF_MBAR, ph0); ph0 ^= 1; }
            else        { mbar_wait(sb + G1_OFF_MBAR + 8, ph1); ph1 ^= 1; }
        }
        char* AoH  = smem + G1_OFF_AH  + s * 16384;
        char* AoL  = smem + G1_OFF_AL  + s * 16384;
        char* B1H  = smem + G1_OFF_B1H + s * 8192;
        char* B1L  = smem + G1_OFF_B1L + s * 8192;
        char* B3H  = smem + G1_OFF_B3H + s * 8192;
        char* B3L  = smem + G1_OFF_B3L + s * 8192;

        // A: 128 rows x 64 floats gathered -> bf16 hi/lo (2048 float4 loads)
        #pragma unroll
        for (int i = 0; i < 8; i++) {
            int id = tid + 256 * i;
            int row = id >> 4, c4 = id & 15;
            int slot = sslot[row];
            float4 v = make_float4(0.f, 0.f, 0.f, 0.f);
            if (slot >= 0) v = *(const float4*)(x + (size_t)(slot >> 1) * H + k0 + c4 * 4);
            uint16_t h[4], l[4];
            #pragma unroll
            for (int j = 0; j < 4; j++) bf16_split((&v.x)[j], h[j], l[j]);
            uint2 ph_ = make_uint2((uint32_t)h[0] | ((uint32_t)h[1] << 16),
                                   (uint32_t)h[2] | ((uint32_t)h[3] << 16));
            uint2 pl_ = make_uint2((uint32_t)l[0] | ((uint32_t)l[1] << 16),
                                   (uint32_t)l[2] | ((uint32_t)l[3] << 16));
            uint32_t so = swz128(row * 128 + c4 * 8);
            *(uint2*)(AoH + so) = ph_;
            *(uint2*)(AoL + so) = pl_;
        }
        // B1/B3: transpose W[k][n] -> [n rows][k cols] bf16 hi/lo (1024 float4 per mat)
        #pragma unroll
        for (int i = 0; i < 4; i++) {
            int id = tid + 256 * i;
            int k = id >> 4, n4 = id & 15;
            size_t goff = (size_t)(k0 + k) * F + n0 + n4 * 4;
            float4 v1 = *(const float4*)(w1p + goff);
            float4 v3 = *(const float4*)(w3p + goff);
            int nb = n4 * 4;
            #pragma unroll
            for (int j = 0; j < 4; j++) {
                uint32_t so = swz128((nb + j) * 128 + k * 2);
                uint16_t h, l;
                bf16_split((&v1.x)[j], h, l);
                *(uint16_t*)(B1H + so) = h;
                *(uint16_t*)(B1L + so) = l;
                bf16_split((&v3.x)[j], h, l);
                *(uint16_t*)(B3H + so) = h;
                *(uint16_t*)(B3L + so) = l;
            }
        }
        fence_async_shared();
        __syncthreads();
        if (tid == 0) {
            uint64_t adh = make_desc(sb + G1_OFF_AH  + s * 16384);
            uint64_t adl = make_desc(sb + G1_OFF_AL  + s * 16384);
            uint64_t b1h = make_desc(sb + G1_OFF_B1H + s * 8192);
            uint64_t b1l = make_desc(sb + G1_OFF_B1L + s * 8192);
            uint64_t b3h = make_desc(sb + G1_OFF_B3H + s * 8192);
            uint64_t b3l = make_desc(sb + G1_OFF_B3L + s * 8192);
            #pragma unroll
            for (int ks = 0; ks < 4; ks++) {
                uint32_t en0 = (kc == 0 && ks == 0) ? 0u : 1u;
                uint64_t o = ks * 2;
                mma_bf16_ss(tb,      adh + o, b1h + o, en0);
                mma_bf16_ss(tb,      adl + o, b1h + o, 1u);
                mma_bf16_ss(tb,      adh + o, b1l + o, 1u);
                mma_bf16_ss(tb + 64, adh + o, b3h + o, en0);
                mma_bf16_ss(tb + 64, adl + o, b3h + o, 1u);
                mma_bf16_ss(tb + 64, adh + o, b3l + o, 1u);
            }
            mma_commit(sb + G1_OFF_MBAR + 8 * s);
        }
    }
    {
        int sl = (NC1 - 1) & 1;
        if (sl == 0) mbar_wait(sb + G1_OFF_MBAR, ph0);
        else         mbar_wait(sb + G1_OFF_MBAR + 8, ph1);
    }
    fence_tc_after();

    if (wid < 4) {
        int m = wid * 32 + lane;
        int slot = sslot[m];
        #pragma unroll
        for (int hlf = 0; hlf < 2; hlf++) {
            uint32_t r1[32], r3[32];
            ldtm_x32(r1, tb + hlf * 32);
            ldtm_x32(r3, tb + 64 + hlf * 32);
            tmem_wait_ld();
            if (slot >= 0) {
                float* dst = g_hmid + (size_t)slot * F + n0 + hlf * 32;
                #pragma unroll
                for (int c = 0; c < 32; c += 4) {
                    float4 o;
                    #pragma unroll
                    for (int j = 0; j < 4; j++) {
                        float g = __uint_as_float(r1[c + j]);
                        float u = __uint_as_float(r3[c + j]);
                        float sg = g / (1.f + expf(-g));
                        (&o.x)[j] = sg * u;
                    }
                    *(float4*)(dst + c) = o;
                }
            }
        }
    }
    __syncthreads();
    if (wid == 0) tmem_dealloc(tb, 128);
#else
    // ---------- SIMT fallback ----------
    int e   = blockIdx.z;
    int cnt = g_count[e];
    int m0  = blockIdx.y * BM;
    if (m0 >= cnt) return;
    int n0  = blockIdx.x * BN;

    __shared__ float Xs[BM][33];
    __shared__ float B1s[32][BN];
    __shared__ float B3s[32][BN];
    __shared__ int   stok[BM];
    __shared__ int   sslot[BM];

    int tid = threadIdx.x;
    for (int i = tid; i < BM; i += 256) {
        int r = m0 + i;
        int slot = (r < cnt) ? g_list[e][r] : -1;
        sslot[i] = slot;
        stok[i]  = (slot >= 0) ? (slot >> 1) : -1;
    }
    __syncthreads();

    int tx = tid & 15, ty = tid >> 4;
    float acc1[8][4], acc3[8][4];
    #pragma unroll
    for (int i = 0; i < 8; i++)
        #pragma unroll
        for (int j = 0; j < 4; j++) { acc1[i][j] = 0.f; acc3[i][j] = 0.f; }

    const float* w1p = W1 + (size_t)e * H * F;
    const float* w3p = W3 + (size_t)e * H * F;

    for (int k0 = 0; k0 < H; k0 += 32) {
        for (int i = tid; i < BM * 32; i += 256) {
            int m = i >> 5, k = i & 31;
            int tok = stok[m];
            Xs[m][k] = (tok >= 0) ? x[(size_t)tok * H + k0 + k] : 0.f;
        }
        for (int i = tid; i < 32 * BN; i += 256) {
            int k = i >> 6, n = i & 63;
            size_t off = (size_t)(k0 + k) * F + n0 + n;
            B1s[k][n] = w1p[off];
            B3s[k][n] = w3p[off];
        }
        __syncthreads();
        #pragma unroll
        for (int kk = 0; kk < 32; kk++) {
            float a[8], b1[4], b3[4];
            #pragma unroll
            for (int i = 0; i < 8; i++) a[i] = Xs[ty + 16 * i][kk];
            #pragma unroll
            for (int j = 0; j < 4; j++) { b1[j] = B1s[kk][tx + 16 * j]; b3[j] = B3s[kk][tx + 16 * j]; }
            #pragma unroll
            for (int i = 0; i < 8; i++)
                #pragma unroll
                for (int j = 0; j < 4; j++) {
                    acc1[i][j] += a[i] * b1[j];
                    acc3[i][j] += a[i] * b3[j];
                }
        }
        __syncthreads();
    }
    #pragma unroll
    for (int i = 0; i < 8; i++) {
        int m = ty + 16 * i;
        int slot = sslot[m];
        if (slot < 0) continue;
        float* dst = g_hmid + (size_t)slot * F + n0;
        #pragma unroll
        for (int j = 0; j < 4; j++) {
            float g = acc1[i][j];
            float u = acc3[i][j];
            float sg = g / (1.f + expf(-g));
            dst[tx + 16 * j] = sg * u;
        }
    }
#endif
}

#define G2_OFF_TMEM 0
#define G2_OFF_MBAR 16
#define G2_OFF_SLOT 64
#define G2_OFF_AH   1024
#define G2_OFF_AL   (G2_OFF_AH + 2*16384)
#define G2_OFF_BH   (G2_OFF_AL + 2*16384)
#define G2_OFF_BL   (G2_OFF_BH + 2*8192)
#define G2_SMEM     (G2_OFF_BL + 2*8192)

__global__ __launch_bounds__(256) void expert_down_mma(
    const float* __restrict__ W2)
{
#if HAS_TCGEN05
    extern __shared__ char smem[];
    int e   = blockIdx.z;
    int cnt = g_count[e];
    int m0  = blockIdx.y * BM;
    if (m0 >= cnt) return;
    int n0  = blockIdx.x * BN;

    uint32_t sb = smem_u32(smem);
    int tid = threadIdx.x, wid = tid >> 5, lane = tid & 31;
    int* sslot = (int*)(smem + G2_OFF_SLOT);
    if (tid < BM) { int r = m0 + tid; sslot[tid] = (r < cnt) ? g_list[e][r] : -1; }
    if (tid == 0) { mbar_init(sb + G2_OFF_MBAR, 1); mbar_init(sb + G2_OFF_MBAR + 8, 1); }
    if (wid == 0) tmem_alloc(sb + G2_OFF_TMEM, 64);
    __syncthreads();
    uint32_t tb;
    asm volatile("ld.shared.b32 %0, [%1];" : "=r"(tb) : "r"(sb + G2_OFF_TMEM));

    const float* w2p = W2 + (size_t)e * F * H;

    int ph0 = 0, ph1 = 0;
    for (int kc = 0; kc < NC2; kc++) {
        int s = kc & 1;
        int k0 = kc * BK;
        if (kc >= 2) {
            if (s == 0) { mbar_wait(sb + G2_OFF_MBAR, ph0); ph0 ^= 1; }
            else        { mbar_wait(sb + G2_OFF_MBAR + 8, ph1); ph1 ^= 1; }
        }
        char* AoH = smem + G2_OFF_AH + s * 16384;
        char* AoL = smem + G2_OFF_AL + s * 16384;
        char* BoH = smem + G2_OFF_BH + s * 8192;
        char* BoL = smem + G2_OFF_BL + s * 8192;

        #pragma unroll
        for (int i = 0; i < 8; i++) {
            int id = tid + 256 * i;
            int row = id >> 4, c4 = id & 15;
            int slot = sslot[row];
            float4 v = make_float4(0.f, 0.f, 0.f, 0.f);
            if (slot >= 0) v = *(const float4*)(g_hmid + (size_t)slot * F + k0 + c4 * 4);
            uint16_t h[4], l[4];
            #pragma unroll
            for (int j = 0; j < 4; j++) bf16_split((&v.x)[j], h[j], l[j]);
            uint2 ph_ = make_uint2((uint32_t)h[0] | ((uint32_t)h[1] << 16),
                                   (uint32_t)h[2] | ((uint32_t)h[3] << 16));
            uint2 pl_ = make_uint2((uint32_t)l[0] | ((uint32_t)l[1] << 16),
                                   (uint32_t)l[2] | ((uint32_t)l[3] << 16));
            uint32_t so = swz128(row * 128 + c4 * 8);
            *(uint2*)(AoH + so) = ph_;
            *(uint2*)(AoL + so) = pl_;
        }
        #pragma unroll
        for (int i = 0; i < 4; i++) {
            int id = tid + 256 * i;
            int k = id >> 4, n4 = id & 15;
            float4 v = *(const float4*)(w2p + (size_t)(k0 + k) * H + n0 + n4 * 4);
            int nb = n4 * 4;
            #pragma unroll
            for (int j = 0; j < 4; j++) {
                uint32_t so = swz128((nb + j) * 128 + k * 2);
                uint16_t h, l;
                bf16_split((&v.x)[j], h, l);
                *(uint16_t*)(BoH + so) = h;
                *(uint16_t*)(BoL + so) = l;
            }
        }
        fence_async_shared();
        __syncthreads();
        if (tid == 0) {
            uint64_t adh = make_desc(sb + G2_OFF_AH + s * 16384);
            uint64_t adl = make_desc(sb + G2_OFF_AL + s * 16384);
            uint64_t bdh = make_desc(sb + G2_OFF_BH + s * 8192);
            uint64_t bdl = make_desc(sb + G2_OFF_BL + s * 8192);
            #pragma unroll
            for (int ks = 0; ks < 4; ks++) {
                uint32_t en0 = (kc == 0 && ks == 0) ? 0u : 1u;
                uint64_t o = ks * 2;
                mma_bf16_ss(tb, adh + o, bdh + o, en0);
                mma_bf16_ss(tb, adl + o, bdh + o, 1u);
                mma_bf16_ss(tb, adh + o, bdl + o, 1u);
            }
            mma_commit(sb + G2_OFF_MBAR + 8 * s);
        }
    }
    {
        int sl = (NC2 - 1) & 1;
        if (sl == 0) mbar_wait(sb + G2_OFF_MBAR, ph0);
        else         mbar_wait(sb + G2_OFF_MBAR + 8, ph1);
    }
    fence_tc_after();

    if (wid < 4) {
        int m = wid * 32 + lane;
        int slot = sslot[m];
        float gw = (slot >= 0) ? g_wslot[slot] : 0.f;
        #pragma unroll
        for (int hlf = 0; hlf < 2; hlf++) {
            uint32_t r0[32];
            ldtm_x32(r0, tb + hlf * 32);
            tmem_wait_ld();
            if (slot >= 0) {
                float* dst = g_outpair + (size_t)slot * H + n0 + hlf * 32;
                #pragma unroll
                for (int c = 0; c < 32; c += 4) {
                    float4 o;
                    #pragma unroll
                    for (int j = 0; j < 4; j++) (&o.x)[j] = gw * __uint_as_float(r0[c + j]);
                    *(float4*)(dst + c) = o;
                }
            }
        }
    }
    __syncthreads();
    if (wid == 0) tmem_dealloc(tb, 64);
#else
    // ---------- SIMT fallback ----------
    int e   = blockIdx.z;
    int cnt = g_count[e];
    int m0  = blockIdx.y * BM;
    if (m0 >= cnt) return;
    int n0  = blockIdx.x * BN;

    __shared__ float As[BM][33];
    __shared__ float Bs[32][BN];
    __shared__ int   sslot[BM];

    int tid = threadIdx.x;
    for (int i = tid; i < BM; i += 256) {
        int r = m0 + i;
        sslot[i] = (r < cnt) ? g_list[e][r] : -1;
    }
    __syncthreads();

    int tx = tid & 15, ty = tid >> 4;
    float acc[8][4];
    #pragma unroll
    for (int i = 0; i < 8; i++)
        #pragma unroll
        for (int j = 0; j < 4; j++) acc[i][j] = 0.f;

    const float* w2p = W2 + (size_t)e * F * H;

    for (int k0 = 0; k0 < F; k0 += 32) {
        for (int i = tid; i < BM * 32; i += 256) {
            int m = i >> 5, k = i & 31;
            int slot = sslot[m];
            As[m][k] = (slot >= 0) ? g_hmid[(size_t)slot * F + k0 + k] : 0.f;
        }
        for (int i = tid; i < 32 * BN; i += 256) {
            int k = i >> 6, n = i & 63;
            Bs[k][n] = w2p[(size_t)(k0 + k) * H + n0 + n];
        }
        __syncthreads();
        #pragma unroll
        for (int kk = 0; kk < 32; kk++) {
            float a[8], b[4];
            #pragma unroll
            for (int i = 0; i < 8; i++) a[i] = As[ty + 16 * i][kk];
            #pragma unroll
            for (int j = 0; j < 4; j++) b[j] = Bs[kk][tx + 16 * j];
            #pragma unroll
            for (int i = 0; i < 8; i++)
                #pragma unroll
                for (int j = 0; j < 4; j++) acc[i][j] += a[i] * b[j];
        }
        __syncthreads();
    }
    #pragma unroll
    for (int i = 0; i < 8; i++) {
        int m = ty + 16 * i;
        int slot = sslot[m];
        if (slot < 0) continue;
        float gw = g_wslot[slot];
        float* dst = g_outpair + (size_t)slot * H + n0;
        #pragma unroll
        for (int j = 0; j < 4; j++) dst[tx + 16 * j] = gw * acc[i][j];
    }
#endif
}

__global__ __launch_bounds__(256) void combine_kernel(float* __restrict__ out)
{
    int i = blockIdx.x * 256 + threadIdx.x;
    if (i >= T * H) return;
    int t = i >> 10;
    int h = i & (H - 1);
    out[i] = g_outpair[(size_t)(2 * t) * H + h] + g_outpair[(size_t)(2 * t + 1) * H + h];
}

extern "C" void kernel_launch(void* const* d_in, const int* in_sizes, int n_in,
                              void* d_out, int out_size)
{
    const float* x  = (const float*)d_in[0];
    const float* Wr = (const float*)d_in[1];
    const float* W1 = (const float*)d_in[2];
    const float* W2 = (const float*)d_in[3];
    const float* W3 = (const float*)d_in[4];
    float* out = (float*)d_out;

    cudaFuncSetAttribute(expert_up_mma,   cudaFuncAttributeMaxDynamicSharedMemorySize, G1_SMEM);
    cudaFuncSetAttribute(expert_down_mma, cudaFuncAttributeMaxDynamicSharedMemorySize, G2_SMEM);

    zero_counts_kernel<<<1, 32>>>();
    router_kernel<<<T, 256>>>(x, Wr);

    dim3 g1(F / BN, MT_MAX, E);
    expert_up_mma<<<g1, 256, G1_SMEM>>>(x, W1, W3);

    dim3 g2(H / BN, MT_MAX, E);
    expert_down_mma<<<g2, 256, G2_SMEM>>>(W2);

    combine_kernel<<<(T * H + 255) / 256, 256>>>(out);
}

// round 5
// speedup vs baseline: 3.5555x; 2.4452x over previous
#include <cuda_runtime.h>
#include <cuda_bf16.h>
#include <cstdint>
#include <math.h>

#define H 1024
#define F 4096
#define E 8
#define T 2048
#define SLOTS (2*T)

#define BM 128
#define BN1 128
#define BN2 128
#define BK 64
#define NC1 (H/BK)
#define NC2 (F/BK)
#define MT_MAX (T/BM)

#if defined(__CUDA_ARCH_FEAT_SM103_ALL) || defined(__CUDA_ARCH_FEAT_SM100_ALL) || \
    (defined(__CUDA_ARCH_SPECIFIC__) && (__CUDA_ARCH_SPECIFIC__ == 1030)) || \
    (defined(__CUDA_ARCH_FAMILY_SPECIFIC__) && (__CUDA_ARCH_FAMILY_SPECIFIC__ == 1030))
#define HAS_TCGEN05 1
#else
#define HAS_TCGEN05 0
#endif

__device__ int   g_count[E];
__device__ int   g_list[E][T];
__device__ float g_wslot[SLOTS];
__device__ float g_hmid[(size_t)SLOTS * F];      // SIMT fallback path only
__device__ float g_outpair[(size_t)SLOTS * H];

// preconverted bf16 hi/lo planes
__device__ __nv_bfloat16 g_xh[(size_t)T * H],  g_xl[(size_t)T * H];
__device__ __nv_bfloat16 g_w1h[(size_t)E*F*H], g_w1l[(size_t)E*F*H];   // [E][F][H] transposed
__device__ __nv_bfloat16 g_w3h[(size_t)E*F*H], g_w3l[(size_t)E*F*H];   // [E][F][H]
__device__ __nv_bfloat16 g_w2h[(size_t)E*H*F], g_w2l[(size_t)E*H*F];   // [E][H][F] transposed
__device__ __nv_bfloat16 g_hmh[(size_t)SLOTS*F], g_hml[(size_t)SLOTS*F];

__device__ __forceinline__ uint32_t smem_u32(const void* p) {
    uint32_t a;
    asm("{ .reg .u64 t; cvta.to.shared.u64 t, %1; cvt.u32.u64 %0, t; }" : "=r"(a) : "l"(p));
    return a;
}
__device__ __forceinline__ uint32_t swz128(uint32_t o) { return o ^ ((o >> 3) & 0x70); }

__device__ __forceinline__ void bf16_split(float v, uint16_t& hi, uint16_t& lo) {
    __nv_bfloat16 h = __float2bfloat16(v);
    __nv_bfloat16 l = __float2bfloat16(v - __bfloat162float(h));
    hi = __bfloat16_as_ushort(h);
    lo = __bfloat16_as_ushort(l);
}

#if HAS_TCGEN05
static __device__ __forceinline__ uint64_t make_desc(uint32_t addr) {
    const uint64_t base = (uint64_t(2) << 61) | (uint64_t(1) << 46) |
                          (uint64_t(64) << 32) | (uint64_t(1) << 16);
    return base | ((uint64_t)(addr >> 4) & 0x3FFF);
}

#define IDESC_N(N) ((1u << 4) | (1u << 7) | (1u << 10) | (((N) / 8) << 17) | ((BM / 16) << 24))

__device__ __forceinline__ void mma_bf16_ss(uint32_t d, uint64_t ad, uint64_t bd,
                                            uint32_t idesc, uint32_t en) {
    asm volatile(
        "{\n\t.reg .pred p;\n\t"
        "setp.ne.u32 p, %4, 0;\n\t"
        "tcgen05.mma.cta_group::1.kind::f16 [%0], %1, %2, %3, {%5,%5,%5,%5}, p;\n\t}"
        :: "r"(d), "l"(ad), "l"(bd), "r"(idesc), "r"(en), "r"(0u) : "memory");
}
__device__ __forceinline__ void tmem_alloc(uint32_t smem_dst, uint32_t ncols) {
    asm volatile("tcgen05.alloc.cta_group::1.sync.aligned.shared::cta.b32 [%0], %1;"
                 :: "r"(smem_dst), "r"(ncols) : "memory");
}
__device__ __forceinline__ void tmem_dealloc(uint32_t tb, uint32_t ncols) {
    asm volatile("tcgen05.relinquish_alloc_permit.cta_group::1.sync.aligned;");
    asm volatile("tcgen05.dealloc.cta_group::1.sync.aligned.b32 %0, %1;" :: "r"(tb), "r"(ncols));
}
__device__ __forceinline__ void mma_commit(uint32_t mbar) {
    asm volatile("tcgen05.commit.cta_group::1.mbarrier::arrive::one.shared::cluster.b64 [%0];"
                 :: "r"(mbar) : "memory");
}
__device__ __forceinline__ void mbar_init(uint32_t mbar, uint32_t cnt) {
    asm volatile("mbarrier.init.shared.b64 [%0], %1;" :: "r"(mbar), "r"(cnt) : "memory");
}
__device__ __forceinline__ void mbar_wait(uint32_t mbar, uint32_t parity) {
    uint32_t done;
    asm volatile(
        "{\n\t.reg .pred p;\n\t"
        "mbarrier.try_wait.parity.acquire.cta.shared::cta.b64 p, [%1], %2;\n\t"
        "selp.b32 %0, 1, 0, p;\n\t}"
        : "=r"(done) : "r"(mbar), "r"(parity) : "memory");
    if (!done) {
        asm volatile(
            "{\n\t.reg .pred P1;\n\t"
            "W_%=:\n\t"
            "mbarrier.try_wait.parity.acquire.cta.shared::cta.b64 P1, [%0], %1, 0x989680;\n\t"
            "@P1 bra.uni D_%=;\n\t"
            "bra.uni W_%=;\n\t"
            "D_%=:\n\t}"
            :: "r"(mbar), "r"(parity) : "memory");
    }
}
__device__ __forceinline__ void fence_async_shared() {
    asm volatile("fence.proxy.async.shared::cta;" ::: "memory");
}
__device__ __forceinline__ void fence_tc_after() {
    asm volatile("tcgen05.fence::after_thread_sync;" ::: "memory");
}
__device__ __forceinline__ void ldtm_x32(uint32_t* r, uint32_t a) {
    asm volatile(
        "tcgen05.ld.sync.aligned.32x32b.x32.b32 "
        "{%0,%1,%2,%3,%4,%5,%6,%7,%8,%9,%10,%11,%12,%13,%14,%15,"
        "%16,%17,%18,%19,%20,%21,%22,%23,%24,%25,%26,%27,%28,%29,%30,%31}, [%32];"
        : "=r"(r[0]), "=r"(r[1]), "=r"(r[2]), "=r"(r[3]), "=r"(r[4]), "=r"(r[5]),
          "=r"(r[6]), "=r"(r[7]), "=r"(r[8]), "=r"(r[9]), "=r"(r[10]), "=r"(r[11]),
          "=r"(r[12]), "=r"(r[13]), "=r"(r[14]), "=r"(r[15]), "=r"(r[16]), "=r"(r[17]),
          "=r"(r[18]), "=r"(r[19]), "=r"(r[20]), "=r"(r[21]), "=r"(r[22]), "=r"(r[23]),
          "=r"(r[24]), "=r"(r[25]), "=r"(r[26]), "=r"(r[27]), "=r"(r[28]), "=r"(r[29]),
          "=r"(r[30]), "=r"(r[31])
        : "r"(a));
}
__device__ __forceinline__ void tmem_wait_ld() {
    asm volatile("tcgen05.wait::ld.sync.aligned;" ::: "memory");
}
#endif // HAS_TCGEN05

// =============== prep kernels ===============
__global__ void zero_counts_kernel() {
    if (threadIdx.x < E) g_count[threadIdx.x] = 0;
}

__global__ __launch_bounds__(256) void router_kernel(
    const float* __restrict__ x, const float* __restrict__ Wr)
{
    int t = blockIdx.x;
    __shared__ float xs[H];
    __shared__ float logits[E];
    int tid = threadIdx.x;
    for (int i = tid; i < H; i += 256) xs[i] = x[(size_t)t * H + i];
    __syncthreads();
    int w = tid >> 5, lane = tid & 31;
    {
        const float* wr = Wr + w * H;
        float s = 0.f;
        for (int i = lane; i < H; i += 32) s += xs[i] * wr[i];
        #pragma unroll
        for (int off = 16; off; off >>= 1) s += __shfl_xor_sync(0xffffffffu, s, off);
        if (lane == 0) logits[w] = s;
    }
    __syncthreads();
    if (tid == 0) {
        int e0 = 0; float b0 = logits[0];
        #pragma unroll
        for (int e = 1; e < E; e++) if (logits[e] > b0) { b0 = logits[e]; e0 = e; }
        int e1 = -1; float b1 = -3.0e38f;
        #pragma unroll
        for (int e = 0; e < E; e++) if (e != e0 && logits[e] > b1) { b1 = logits[e]; e1 = e; }
        float w0 = 1.f / (1.f + expf(b1 - b0));
        float w1 = 1.f - w0;
        int p0 = atomicAdd(&g_count[e0], 1);
        int p1 = atomicAdd(&g_count[e1], 1);
        g_list[e0][p0] = 2 * t;
        g_list[e1][p1] = 2 * t + 1;
        g_wslot[2 * t]     = w0;
        g_wslot[2 * t + 1] = w1;
    }
}

// x [T,H] fp32 -> g_xh/g_xl bf16 planes (elementwise)
__global__ __launch_bounds__(256) void convert_x_kernel(const float* __restrict__ x)
{
    size_t i = ((size_t)blockIdx.x * 256 + threadIdx.x) * 8;
    float v[8];
    *(float4*)(v)     = *(const float4*)(x + i);
    *(float4*)(v + 4) = *(const float4*)(x + i + 4);
    uint16_t h[8], l[8];
    #pragma unroll
    for (int j = 0; j < 8; j++) bf16_split(v[j], h[j], l[j]);
    uint4 ph = make_uint4((uint32_t)h[0] | ((uint32_t)h[1] << 16),
                          (uint32_t)h[2] | ((uint32_t)h[3] << 16),
                          (uint32_t)h[4] | ((uint32_t)h[5] << 16),
                          (uint32_t)h[6] | ((uint32_t)h[7] << 16));
    uint4 pl = make_uint4((uint32_t)l[0] | ((uint32_t)l[1] << 16),
                          (uint32_t)l[2] | ((uint32_t)l[3] << 16),
                          (uint32_t)l[4] | ((uint32_t)l[5] << 16),
                          (uint32_t)l[6] | ((uint32_t)l[7] << 16));
    *(uint4*)((char*)g_xh + i * 2) = ph;
    *(uint4*)((char*)g_xl + i * 2) = pl;
}

// transpose + split: src [E][K][N] fp32 -> dh/dl [E][N][K] bf16
__global__ __launch_bounds__(256) void transpose_split_kernel(
    const float* __restrict__ src,
    __nv_bfloat16* __restrict__ dh,
    __nv_bfloat16* __restrict__ dl,
    int K, int N)
{
    __shared__ float ts[32][33];
    int e = blockIdx.z;
    size_t base = (size_t)e * K * N;
    int n0 = blockIdx.x * 32, k0 = blockIdx.y * 32;
    int tx = threadIdx.x & 31, ty = threadIdx.x >> 5;  // ty 0..7
    #pragma unroll
    for (int r = 0; r < 4; r++) {
        int k = k0 + ty + 8 * r;
        ts[ty + 8 * r][tx] = src[base + (size_t)k * N + n0 + tx];
    }
    __syncthreads();
    #pragma unroll
    for (int r = 0; r < 4; r++) {
        int n = n0 + ty + 8 * r;
        float v = ts[tx][ty + 8 * r];
        uint16_t h, l;
        bf16_split(v, h, l);
        size_t o = base + (size_t)n * K + k0 + tx;
        *(uint16_t*)(dh + o) = h;
        *(uint16_t*)(dl + o) = l;
    }
}

// =============== GEMM1 ===============
#define G1_OFF_TMEM 0
#define G1_OFF_MBAR 16
#define G1_OFF_SLOT 64
#define G1_OFF_AH   1024
#define G1_OFF_AL   (G1_OFF_AH  + 2*16384)
#define G1_OFF_B1H  (G1_OFF_AL  + 2*16384)
#define G1_OFF_B1L  (G1_OFF_B1H + 2*16384)
#define G1_OFF_B3H  (G1_OFF_B1L + 2*16384)
#define G1_OFF_B3L  (G1_OFF_B3H + 2*16384)
#define G1_SMEM     (G1_OFF_B3L + 2*16384)

__global__ __launch_bounds__(256) void expert_up_mma(
    const float* __restrict__ x,
    const float* __restrict__ W1,
    const float* __restrict__ W3)
{
#if HAS_TCGEN05
    extern __shared__ char smem[];
    int e   = blockIdx.z;
    int cnt = g_count[e];
    int m0  = blockIdx.y * BM;
    if (m0 >= cnt) return;
    int n0  = blockIdx.x * BN1;

    uint32_t sb = smem_u32(smem);
    int tid = threadIdx.x, wid = tid >> 5, lane = tid & 31;
    int* sslot = (int*)(smem + G1_OFF_SLOT);
    if (tid < BM) { int r = m0 + tid; sslot[tid] = (r < cnt) ? g_list[e][r] : -1; }
    if (tid == 0) { mbar_init(sb + G1_OFF_MBAR, 1); mbar_init(sb + G1_OFF_MBAR + 8, 1); }
    if (wid == 0) tmem_alloc(sb + G1_OFF_TMEM, 256);
    __syncthreads();
    uint32_t tb;
    asm volatile("ld.shared.b32 %0, [%1];" : "=r"(tb) : "r"(sb + G1_OFF_TMEM));

    const __nv_bfloat16* w1h = g_w1h + ((size_t)e * F + n0) * H;
    const __nv_bfloat16* w1l = g_w1l + ((size_t)e * F + n0) * H;
    const __nv_bfloat16* w3h = g_w3h + ((size_t)e * F + n0) * H;
    const __nv_bfloat16* w3l = g_w3l + ((size_t)e * F + n0) * H;

    int ph0 = 0, ph1 = 0;
    for (int kc = 0; kc < NC1; kc++) {
        int s = kc & 1;
        int k0 = kc * BK;
        if (kc >= 2) {
            if (s == 0) { mbar_wait(sb + G1_OFF_MBAR, ph0); ph0 ^= 1; }
            else        { mbar_wait(sb + G1_OFF_MBAR + 8, ph1); ph1 ^= 1; }
        }
        char* AoH = smem + G1_OFF_AH  + s * 16384;
        char* AoL = smem + G1_OFF_AL  + s * 16384;
        char* B1H = smem + G1_OFF_B1H + s * 16384;
        char* B1L = smem + G1_OFF_B1L + s * 16384;
        char* B3H = smem + G1_OFF_B3H + s * 16384;
        char* B3L = smem + G1_OFF_B3L + s * 16384;

        // A tiles: gathered rows of x hi/lo. 1024 16B-units per comp.
        #pragma unroll
        for (int i = 0; i < 4; i++) {
            int id = tid + 256 * i;
            int row = id >> 3, c8 = id & 7;
            int slot = sslot[row];
            uint4 vh = make_uint4(0, 0, 0, 0), vl = vh;
            if (slot >= 0) {
                size_t o = (size_t)(slot >> 1) * H + k0 + c8 * 8;
                vh = *(const uint4*)(g_xh + o);
                vl = *(const uint4*)(g_xl + o);
            }
            uint32_t so = swz128(row * 128 + c8 * 16);
            *(uint4*)(AoH + so) = vh;
            *(uint4*)(AoL + so) = vl;
        }
        // B tiles: [n][k] contiguous. 1024 units per comp.
        #pragma unroll
        for (int i = 0; i < 4; i++) {
            int id = tid + 256 * i;
            int row = id >> 3, c8 = id & 7;
            size_t o = (size_t)row * H + k0 + c8 * 8;
            uint32_t so = swz128(row * 128 + c8 * 16);
            *(uint4*)(B1H + so) = *(const uint4*)(w1h + o);
            *(uint4*)(B1L + so) = *(const uint4*)(w1l + o);
            *(uint4*)(B3H + so) = *(const uint4*)(w3h + o);
            *(uint4*)(B3L + so) = *(const uint4*)(w3l + o);
        }
        fence_async_shared();
        __syncthreads();
        if (tid == 0) {
            uint64_t adh = make_desc(sb + G1_OFF_AH  + s * 16384);
            uint64_t adl = make_desc(sb + G1_OFF_AL  + s * 16384);
            uint64_t b1h = make_desc(sb + G1_OFF_B1H + s * 16384);
            uint64_t b1l = make_desc(sb + G1_OFF_B1L + s * 16384);
            uint64_t b3h = make_desc(sb + G1_OFF_B3H + s * 16384);
            uint64_t b3l = make_desc(sb + G1_OFF_B3L + s * 16384);
            #pragma unroll
            for (int ks = 0; ks < 4; ks++) {
                uint32_t en0 = (kc == 0 && ks == 0) ? 0u : 1u;
                uint64_t o = ks * 2;
                mma_bf16_ss(tb,       adh + o, b1h + o, IDESC_N(BN1), en0);
                mma_bf16_ss(tb,       adl + o, b1h + o, IDESC_N(BN1), 1u);
                mma_bf16_ss(tb,       adh + o, b1l + o, IDESC_N(BN1), 1u);
                mma_bf16_ss(tb + 128, adh + o, b3h + o, IDESC_N(BN1), en0);
                mma_bf16_ss(tb + 128, adl + o, b3h + o, IDESC_N(BN1), 1u);
                mma_bf16_ss(tb + 128, adh + o, b3l + o, IDESC_N(BN1), 1u);
            }
            mma_commit(sb + G1_OFF_MBAR + 8 * s);
        }
    }
    {
        int sl = (NC1 - 1) & 1;
        if (sl == 0) mbar_wait(sb + G1_OFF_MBAR, ph0);
        else         mbar_wait(sb + G1_OFF_MBAR + 8, ph1);
    }
    fence_tc_after();

    if (wid < 4) {
        int m = wid * 32 + lane;
        int slot = sslot[m];
        #pragma unroll
        for (int cb = 0; cb < 4; cb++) {
            uint32_t r1[32], r3[32];
            ldtm_x32(r1, tb + cb * 32);
            ldtm_x32(r3, tb + 128 + cb * 32);
            tmem_wait_ld();
            if (slot >= 0) {
                char* dh = (char*)(g_hmh + (size_t)slot * F + n0 + cb * 32);
                char* dl = (char*)(g_hml + (size_t)slot * F + n0 + cb * 32);
                #pragma unroll
                for (int c = 0; c < 32; c += 2) {
                    float g0 = __uint_as_float(r1[c]),     u0 = __uint_as_float(r3[c]);
                    float g1 = __uint_as_float(r1[c + 1]), u1 = __uint_as_float(r3[c + 1]);
                    float v0 = (g0 / (1.f + expf(-g0))) * u0;
                    float v1 = (g1 / (1.f + expf(-g1))) * u1;
                    uint16_t h0, l0, h1, l1;
                    bf16_split(v0, h0, l0);
                    bf16_split(v1, h1, l1);
                    *(uint32_t*)(dh + c * 2) = (uint32_t)h0 | ((uint32_t)h1 << 16);
                    *(uint32_t*)(dl + c * 2) = (uint32_t)l0 | ((uint32_t)l1 << 16);
                }
            }
        }
    }
    __syncthreads();
    if (wid == 0) tmem_dealloc(tb, 256);
#else
    // ---------- SIMT fallback (two 64-wide halves of the 128 tile) ----------
    int e   = blockIdx.z;
    int cnt = g_count[e];
    int m0  = blockIdx.y * BM;
    if (m0 >= cnt) return;

    __shared__ float Xs[BM][33];
    __shared__ float B1s[32][64];
    __shared__ float B3s[32][64];
    __shared__ int   stok[BM];
    __shared__ int   sslot[BM];

    int tid = threadIdx.x;
    for (int i = tid; i < BM; i += 256) {
        int r = m0 + i;
        int slot = (r < cnt) ? g_list[e][r] : -1;
        sslot[i] = slot;
        stok[i]  = (slot >= 0) ? (slot >> 1) : -1;
    }
    __syncthreads();

    const float* w1p = W1 + (size_t)e * H * F;
    const float* w3p = W3 + (size_t)e * H * F;
    int tx = tid & 15, ty = tid >> 4;

    for (int half = 0; half < 2; half++) {
        int n0 = blockIdx.x * BN1 + half * 64;
        float acc1[8][4], acc3[8][4];
        #pragma unroll
        for (int i = 0; i < 8; i++)
            #pragma unroll
            for (int j = 0; j < 4; j++) { acc1[i][j] = 0.f; acc3[i][j] = 0.f; }

        for (int k0 = 0; k0 < H; k0 += 32) {
            __syncthreads();
            for (int i = tid; i < BM * 32; i += 256) {
                int m = i >> 5, k = i & 31;
                int tok = stok[m];
                Xs[m][k] = (tok >= 0) ? x[(size_t)tok * H + k0 + k] : 0.f;
            }
            for (int i = tid; i < 32 * 64; i += 256) {
                int k = i >> 6, n = i & 63;
                size_t off = (size_t)(k0 + k) * F + n0 + n;
                B1s[k][n] = w1p[off];
                B3s[k][n] = w3p[off];
            }
            __syncthreads();
            #pragma unroll
            for (int kk = 0; kk < 32; kk++) {
                float a[8], b1[4], b3[4];
                #pragma unroll
                for (int i = 0; i < 8; i++) a[i] = Xs[ty + 16 * i][kk];
                #pragma unroll
                for (int j = 0; j < 4; j++) { b1[j] = B1s[kk][tx + 16 * j]; b3[j] = B3s[kk][tx + 16 * j]; }
                #pragma unroll
                for (int i = 0; i < 8; i++)
                    #pragma unroll
                    for (int j = 0; j < 4; j++) {
                        acc1[i][j] += a[i] * b1[j];
                        acc3[i][j] += a[i] * b3[j];
                    }
            }
        }
        #pragma unroll
        for (int i = 0; i < 8; i++) {
            int m = ty + 16 * i;
            int slot = sslot[m];
            if (slot < 0) continue;
            float* dst = g_hmid + (size_t)slot * F + n0;
            #pragma unroll
            for (int j = 0; j < 4; j++) {
                float g = acc1[i][j];
                float u = acc3[i][j];
                float sg = g / (1.f + expf(-g));
                dst[tx + 16 * j] = sg * u;
            }
        }
        __syncthreads();
    }
#endif
}

// =============== GEMM2 ===============
#define G2_OFF_TMEM 0
#define G2_OFF_MBAR 16
#define G2_OFF_SLOT 64
#define G2_OFF_AH   1024
#define G2_OFF_AL   (G2_OFF_AH + 2*16384)
#define G2_OFF_BH   (G2_OFF_AL + 2*16384)
#define G2_OFF_BL   (G2_OFF_BH + 2*16384)
#define G2_SMEM     (G2_OFF_BL + 2*16384)

__global__ __launch_bounds__(256) void expert_down_mma(
    const float* __restrict__ W2)
{
#if HAS_TCGEN05
    extern __shared__ char smem[];
    int e   = blockIdx.z;
    int cnt = g_count[e];
    int m0  = blockIdx.y * BM;
    if (m0 >= cnt) return;
    int n0  = blockIdx.x * BN2;

    uint32_t sb = smem_u32(smem);
    int tid = threadIdx.x, wid = tid >> 5, lane = tid & 31;
    int* sslot = (int*)(smem + G2_OFF_SLOT);
    if (tid < BM) { int r = m0 + tid; sslot[tid] = (r < cnt) ? g_list[e][r] : -1; }
    if (tid == 0) { mbar_init(sb + G2_OFF_MBAR, 1); mbar_init(sb + G2_OFF_MBAR + 8, 1); }
    if (wid == 0) tmem_alloc(sb + G2_OFF_TMEM, 128);
    __syncthreads();
    uint32_t tb;
    asm volatile("ld.shared.b32 %0, [%1];" : "=r"(tb) : "r"(sb + G2_OFF_TMEM));

    const __nv_bfloat16* w2h = g_w2h + ((size_t)e * H + n0) * F;
    const __nv_bfloat16* w2l = g_w2l + ((size_t)e * H + n0) * F;

    int ph0 = 0, ph1 = 0;
    for (int kc = 0; kc < NC2; kc++) {
        int s = kc & 1;
        int k0 = kc * BK;
        if (kc >= 2) {
            if (s == 0) { mbar_wait(sb + G2_OFF_MBAR, ph0); ph0 ^= 1; }
            else        { mbar_wait(sb + G2_OFF_MBAR + 8, ph1); ph1 ^= 1; }
        }
        char* AoH = smem + G2_OFF_AH + s * 16384;
        char* AoL = smem + G2_OFF_AL + s * 16384;
        char* BoH = smem + G2_OFF_BH + s * 16384;
        char* BoL = smem + G2_OFF_BL + s * 16384;

        #pragma unroll
        for (int i = 0; i < 4; i++) {
            int id = tid + 256 * i;
            int row = id >> 3, c8 = id & 7;
            int slot = sslot[row];
            uint4 vh = make_uint4(0, 0, 0, 0), vl = vh;
            if (slot >= 0) {
                size_t o = (size_t)slot * F + k0 + c8 * 8;
                vh = *(const uint4*)(g_hmh + o);
                vl = *(const uint4*)(g_hml + o);
            }
            uint32_t so = swz128(row * 128 + c8 * 16);
            *(uint4*)(AoH + so) = vh;
            *(uint4*)(AoL + so) = vl;
        }
        #pragma unroll
        for (int i = 0; i < 4; i++) {
            int id = tid + 256 * i;
            int row = id >> 3, c8 = id & 7;
            size_t o = (size_t)row * F + k0 + c8 * 8;
            uint32_t so = swz128(row * 128 + c8 * 16);
            *(uint4*)(BoH + so) = *(const uint4*)(w2h + o);
            *(uint4*)(BoL + so) = *(const uint4*)(w2l + o);
        }
        fence_async_shared();
        __syncthreads();
        if (tid == 0) {
            uint64_t adh = make_desc(sb + G2_OFF_AH + s * 16384);
            uint64_t adl = make_desc(sb + G2_OFF_AL + s * 16384);
            uint64_t bdh = make_desc(sb + G2_OFF_BH + s * 16384);
            uint64_t bdl = make_desc(sb + G2_OFF_BL + s * 16384);
            #pragma unroll
            for (int ks = 0; ks < 4; ks++) {
                uint32_t en0 = (kc == 0 && ks == 0) ? 0u : 1u;
                uint64_t o = ks * 2;
                mma_bf16_ss(tb, adh + o, bdh + o, IDESC_N(BN2), en0);
                mma_bf16_ss(tb, adl + o, bdh + o, IDESC_N(BN2), 1u);
                mma_bf16_ss(tb, adh + o, bdl + o, IDESC_N(BN2), 1u);
            }
            mma_commit(sb + G2_OFF_MBAR + 8 * s);
        }
    }
    {
        int sl = (NC2 - 1) & 1;
        if (sl == 0) mbar_wait(sb + G2_OFF_MBAR, ph0);
        else         mbar_wait(sb + G2_OFF_MBAR + 8, ph1);
    }
    fence_tc_after();

    if (wid < 4) {
        int m = wid * 32 + lane;
        int slot = sslot[m];
        float gw = (slot >= 0) ? g_wslot[slot] : 0.f;
        #pragma unroll
        for (int cb = 0; cb < 4; cb++) {
            uint32_t r0[32];
            ldtm_x32(r0, tb + cb * 32);
            tmem_wait_ld();
            if (slot >= 0) {
                float* dst = g_outpair + (size_t)slot * H + n0 + cb * 32;
                #pragma unroll
                for (int c = 0; c < 32; c += 4) {
                    float4 o;
                    #pragma unroll
                    for (int j = 0; j < 4; j++) (&o.x)[j] = gw * __uint_as_float(r0[c + j]);
                    *(float4*)(dst + c) = o;
                }
            }
        }
    }
    __syncthreads();
    if (wid == 0) tmem_dealloc(tb, 128);
#else
    // ---------- SIMT fallback ----------
    int e   = blockIdx.z;
    int cnt = g_count[e];
    int m0  = blockIdx.y * BM;
    if (m0 >= cnt) return;

    __shared__ float As[BM][33];
    __shared__ float Bs[32][64];
    __shared__ int   sslot[BM];

    int tid = threadIdx.x;
    for (int i = tid; i < BM; i += 256) {
        int r = m0 + i;
        sslot[i] = (r < cnt) ? g_list[e][r] : -1;
    }
    __syncthreads();

    const float* w2p = W2 + (size_t)e * F * H;
    int tx = tid & 15, ty = tid >> 4;

    for (int half = 0; half < 2; half++) {
        int n0 = blockIdx.x * BN2 + half * 64;
        float acc[8][4];
        #pragma unroll
        for (int i = 0; i < 8; i++)
            #pragma unroll
            for (int j = 0; j < 4; j++) acc[i][j] = 0.f;

        for (int k0 = 0; k0 < F; k0 += 32) {
            __syncthreads();
            for (int i = tid; i < BM * 32; i += 256) {
                int m = i >> 5, k = i & 31;
                int slot = sslot[m];
                As[m][k] = (slot >= 0) ? g_hmid[(size_t)slot * F + k0 + k] : 0.f;
            }
            for (int i = tid; i < 32 * 64; i += 256) {
                int k = i >> 6, n = i & 63;
                Bs[k][n] = w2p[(size_t)(k0 + k) * H + n0 + n];
            }
            __syncthreads();
            #pragma unroll
            for (int kk = 0; kk < 32; kk++) {
                float a[8], b[4];
                #pragma unroll
                for (int i = 0; i < 8; i++) a[i] = As[ty + 16 * i][kk];
                #pragma unroll
                for (int j = 0; j < 4; j++) b[j] = Bs[kk][tx + 16 * j];
                #pragma unroll
                for (int i = 0; i < 8; i++)
                    #pragma unroll
                    for (int j = 0; j < 4; j++) acc[i][j] += a[i] * b[j];
            }
        }
        #pragma unroll
        for (int i = 0; i < 8; i++) {
            int m = ty + 16 * i;
            int slot = sslot[m];
            if (slot < 0) continue;
            float gw = g_wslot[slot];
            float* dst = g_outpair + (size_t)slot * H + n0;
            #pragma unroll
            for (int j = 0; j < 4; j++) dst[tx + 16 * j] = gw * acc[i][j];
        }
        __syncthreads();
    }
#endif
}

__global__ __launch_bounds__(256) void combine_kernel(float* __restrict__ out)
{
    int i = blockIdx.x * 256 + threadIdx.x;
    if (i >= T * H) return;
    int t = i >> 10;
    int h = i & (H - 1);
    out[i] = g_outpair[(size_t)(2 * t) * H + h] + g_outpair[(size_t)(2 * t + 1) * H + h];
}

extern "C" void kernel_launch(void* const* d_in, const int* in_sizes, int n_in,
                              void* d_out, int out_size)
{
    const float* x  = (const float*)d_in[0];
    const float* Wr = (const float*)d_in[1];
    const float* W1 = (const float*)d_in[2];
    const float* W2 = (const float*)d_in[3];
    const float* W3 = (const float*)d_in[4];
    float* out = (float*)d_out;

    __nv_bfloat16 *w1h, *w1l, *w3h, *w3l, *w2h, *w2l;
    cudaGetSymbolAddress((void**)&w1h, g_w1h);
    cudaGetSymbolAddress((void**)&w1l, g_w1l);
    cudaGetSymbolAddress((void**)&w3h, g_w3h);
    cudaGetSymbolAddress((void**)&w3l, g_w3l);
    cudaGetSymbolAddress((void**)&w2h, g_w2h);
    cudaGetSymbolAddress((void**)&w2l, g_w2l);

    cudaFuncSetAttribute(expert_up_mma,   cudaFuncAttributeMaxDynamicSharedMemorySize, G1_SMEM);
    cudaFuncSetAttribute(expert_down_mma, cudaFuncAttributeMaxDynamicSharedMemorySize, G2_SMEM);

    zero_counts_kernel<<<1, 32>>>();
    router_kernel<<<T, 256>>>(x, Wr);

    convert_x_kernel<<<(T * H) / (256 * 8), 256>>>(x);
    {
        dim3 gw13(F / 32, H / 32, E);   // src [H][F] -> dst [F][H]
        transpose_split_kernel<<<gw13, 256>>>(W1, w1h, w1l, H, F);
        transpose_split_kernel<<<gw13, 256>>>(W3, w3h, w3l, H, F);
        dim3 gw2(H / 32, F / 32, E);    // src [F][H] -> dst [H][F]
        transpose_split_kernel<<<gw2, 256>>>(W2, w2h, w2l, F, H);
    }

    dim3 g1(F / BN1, MT_MAX, E);
    expert_up_mma<<<g1, 256, G1_SMEM>>>(x, W1, W3);

    dim3 g2(H / BN2, MT_MAX, E);
    expert_down_mma<<<g2, 256, G2_SMEM>>>(W2);

    combine_kernel<<<(T * H + 255) / 256, 256>>>(out);
}

// round 6
// speedup vs baseline: 3.7395x; 1.0517x over previous
#include <cuda_runtime.h>
#include <cuda.h>
#include <cuda_bf16.h>
#include <cstdint>
#include <math.h>

#define H 1024
#define F 4096
#define E 8
#define T 2048
#define SLOTS (2*T)

#define BM 128
#define BN1 128
#define BN2 128
#define BK 64
#define NC1 (H/BK)
#define NC2 (F/BK)
#define MT_MAX (T/BM)

#if defined(__CUDA_ARCH_FEAT_SM103_ALL) || defined(__CUDA_ARCH_FEAT_SM100_ALL) || \
    (defined(__CUDA_ARCH_SPECIFIC__) && (__CUDA_ARCH_SPECIFIC__ == 1030)) || \
    (defined(__CUDA_ARCH_FAMILY_SPECIFIC__) && (__CUDA_ARCH_FAMILY_SPECIFIC__ == 1030))
#define HAS_TCGEN05 1
#else
#define HAS_TCGEN05 0
#endif

__device__ int   g_count[E];
__device__ int   g_list[E][T];
__device__ float g_wslot[SLOTS];
__device__ float g_hmid[(size_t)SLOTS * F];      // SIMT fallback path only
__device__ float g_outpair[(size_t)SLOTS * H];

__device__ __nv_bfloat16 g_xh[(size_t)T * H],  g_xl[(size_t)T * H];
__device__ __nv_bfloat16 g_w1h[(size_t)E*F*H], g_w1l[(size_t)E*F*H];   // [E][F][H]
__device__ __nv_bfloat16 g_w3h[(size_t)E*F*H], g_w3l[(size_t)E*F*H];   // [E][F][H]
__device__ __nv_bfloat16 g_w2h[(size_t)E*H*F], g_w2l[(size_t)E*H*F];   // [E][H][F]
__device__ __nv_bfloat16 g_hmh[(size_t)SLOTS*F], g_hml[(size_t)SLOTS*F];

__device__ __forceinline__ uint32_t smem_u32(const void* p) {
    uint32_t a;
    asm("{ .reg .u64 t; cvta.to.shared.u64 t, %1; cvt.u32.u64 %0, t; }" : "=r"(a) : "l"(p));
    return a;
}
__device__ __forceinline__ uint32_t swz128(uint32_t o) { return o ^ ((o >> 3) & 0x70); }

__device__ __forceinline__ void bf16_split(float v, uint16_t& hi, uint16_t& lo) {
    __nv_bfloat16 h = __float2bfloat16(v);
    __nv_bfloat16 l = __float2bfloat16(v - __bfloat162float(h));
    hi = __bfloat16_as_ushort(h);
    lo = __bfloat16_as_ushort(l);
}

#if HAS_TCGEN05
static __device__ __forceinline__ uint64_t make_desc(uint32_t addr) {
    const uint64_t base = (uint64_t(2) << 61) | (uint64_t(1) << 46) |
                          (uint64_t(64) << 32) | (uint64_t(1) << 16);
    return base | ((uint64_t)(addr >> 4) & 0x3FFF);
}

#define IDESC_N(N) ((1u << 4) | (1u << 7) | (1u << 10) | (((N) / 8) << 17) | ((BM / 16) << 24))

__device__ __forceinline__ void mma_bf16_ss(uint32_t d, uint64_t ad, uint64_t bd,
                                            uint32_t idesc, uint32_t en) {
    asm volatile(
        "{\n\t.reg .pred p;\n\t"
        "setp.ne.u32 p, %4, 0;\n\t"
        "tcgen05.mma.cta_group::1.kind::f16 [%0], %1, %2, %3, {%5,%5,%5,%5}, p;\n\t}"
        :: "r"(d), "l"(ad), "l"(bd), "r"(idesc), "r"(en), "r"(0u) : "memory");
}
__device__ __forceinline__ void tmem_alloc(uint32_t smem_dst, uint32_t ncols) {
    asm volatile("tcgen05.alloc.cta_group::1.sync.aligned.shared::cta.b32 [%0], %1;"
                 :: "r"(smem_dst), "r"(ncols) : "memory");
}
__device__ __forceinline__ void tmem_dealloc(uint32_t tb, uint32_t ncols) {
    asm volatile("tcgen05.relinquish_alloc_permit.cta_group::1.sync.aligned;");
    asm volatile("tcgen05.dealloc.cta_group::1.sync.aligned.b32 %0, %1;" :: "r"(tb), "r"(ncols));
}
__device__ __forceinline__ void mma_commit(uint32_t mbar) {
    asm volatile("tcgen05.commit.cta_group::1.mbarrier::arrive::one.shared::cluster.b64 [%0];"
                 :: "r"(mbar) : "memory");
}
__device__ __forceinline__ void mbar_init(uint32_t mbar, uint32_t cnt) {
    asm volatile("mbarrier.init.shared.b64 [%0], %1;" :: "r"(mbar), "r"(cnt) : "memory");
}
__device__ __forceinline__ void mbar_wait(uint32_t mbar, uint32_t parity) {
    uint32_t done;
    asm volatile(
        "{\n\t.reg .pred p;\n\t"
        "mbarrier.try_wait.parity.acquire.cta.shared::cta.b64 p, [%1], %2;\n\t"
        "selp.b32 %0, 1, 0, p;\n\t}"
        : "=r"(done) : "r"(mbar), "r"(parity) : "memory");
    if (!done) {
        asm volatile(
            "{\n\t.reg .pred P1;\n\t"
            "W_%=:\n\t"
            "mbarrier.try_wait.parity.acquire.cta.shared::cta.b64 P1, [%0], %1, 0x989680;\n\t"
            "@P1 bra.uni D_%=;\n\t"
            "bra.uni W_%=;\n\t"
            "D_%=:\n\t}"
            :: "r"(mbar), "r"(parity) : "memory");
    }
}
__device__ __forceinline__ void mbar_expect_tx(uint32_t mbar, uint32_t bytes) {
    asm volatile("mbarrier.arrive.expect_tx.shared.b64 _, [%0], %1;"
                 :: "r"(mbar), "r"(bytes) : "memory");
}
__device__ __forceinline__ void tma_2d(uint32_t dst, const CUtensorMap* map,
                                       int x, int y, uint32_t mbar) {
    asm volatile(
        "cp.async.bulk.tensor.2d.shared::cta.global.tile.mbarrier::complete_tx::bytes "
        "[%0], [%1, {%2, %3}], [%4];"
        :: "r"(dst), "l"(map), "r"(x), "r"(y), "r"(mbar) : "memory");
}
__device__ __forceinline__ void fence_async_shared() {
    asm volatile("fence.proxy.async.shared::cta;" ::: "memory");
}
__device__ __forceinline__ void fence_tc_after() {
    asm volatile("tcgen05.fence::after_thread_sync;" ::: "memory");
}
__device__ __forceinline__ void ldtm_x32(uint32_t* r, uint32_t a) {
    asm volatile(
        "tcgen05.ld.sync.aligned.32x32b.x32.b32 "
        "{%0,%1,%2,%3,%4,%5,%6,%7,%8,%9,%10,%11,%12,%13,%14,%15,"
        "%16,%17,%18,%19,%20,%21,%22,%23,%24,%25,%26,%27,%28,%29,%30,%31}, [%32];"
        : "=r"(r[0]), "=r"(r[1]), "=r"(r[2]), "=r"(r[3]), "=r"(r[4]), "=r"(r[5]),
          "=r"(r[6]), "=r"(r[7]), "=r"(r[8]), "=r"(r[9]), "=r"(r[10]), "=r"(r[11]),
          "=r"(r[12]), "=r"(r[13]), "=r"(r[14]), "=r"(r[15]), "=r"(r[16]), "=r"(r[17]),
          "=r"(r[18]), "=r"(r[19]), "=r"(r[20]), "=r"(r[21]), "=r"(r[22]), "=r"(r[23]),
          "=r"(r[24]), "=r"(r[25]), "=r"(r[26]), "=r"(r[27]), "=r"(r[28]), "=r"(r[29]),
          "=r"(r[30]), "=r"(r[31])
        : "r"(a));
}
__device__ __forceinline__ void tmem_wait_ld() {
    asm volatile("tcgen05.wait::ld.sync.aligned;" ::: "memory");
}
#endif // HAS_TCGEN05

// =============== prep kernels ===============
__global__ void zero_counts_kernel() {
    if (threadIdx.x < E) g_count[threadIdx.x] = 0;
}

__global__ __launch_bounds__(256) void router_kernel(
    const float* __restrict__ x, const float* __restrict__ Wr)
{
    int t = blockIdx.x;
    __shared__ float xs[H];
    __shared__ float logits[E];
    int tid = threadIdx.x;
    for (int i = tid; i < H; i += 256) xs[i] = x[(size_t)t * H + i];
    __syncthreads();
    int w = tid >> 5, lane = tid & 31;
    {
        const float* wr = Wr + w * H;
        float s = 0.f;
        for (int i = lane; i < H; i += 32) s += xs[i] * wr[i];
        #pragma unroll
        for (int off = 16; off; off >>= 1) s += __shfl_xor_sync(0xffffffffu, s, off);
        if (lane == 0) logits[w] = s;
    }
    __syncthreads();
    if (tid == 0) {
        int e0 = 0; float b0 = logits[0];
        #pragma unroll
        for (int e = 1; e < E; e++) if (logits[e] > b0) { b0 = logits[e]; e0 = e; }
        int e1 = -1; float b1 = -3.0e38f;
        #pragma unroll
        for (int e = 0; e < E; e++) if (e != e0 && logits[e] > b1) { b1 = logits[e]; e1 = e; }
        float w0 = 1.f / (1.f + expf(b1 - b0));
        float w1 = 1.f - w0;
        int p0 = atomicAdd(&g_count[e0], 1);
        int p1 = atomicAdd(&g_count[e1], 1);
        g_list[e0][p0] = 2 * t;
        g_list[e1][p1] = 2 * t + 1;
        g_wslot[2 * t]     = w0;
        g_wslot[2 * t + 1] = w1;
    }
}

__global__ __launch_bounds__(256) void convert_x_kernel(const float* __restrict__ x)
{
    size_t i = ((size_t)blockIdx.x * 256 + threadIdx.x) * 8;
    float v[8];
    *(float4*)(v)     = *(const float4*)(x + i);
    *(float4*)(v + 4) = *(const float4*)(x + i + 4);
    uint16_t h[8], l[8];
    #pragma unroll
    for (int j = 0; j < 8; j++) bf16_split(v[j], h[j], l[j]);
    uint4 ph = make_uint4((uint32_t)h[0] | ((uint32_t)h[1] << 16),
                          (uint32_t)h[2] | ((uint32_t)h[3] << 16),
                          (uint32_t)h[4] | ((uint32_t)h[5] << 16),
                          (uint32_t)h[6] | ((uint32_t)h[7] << 16));
    uint4 pl = make_uint4((uint32_t)l[0] | ((uint32_t)l[1] << 16),
                          (uint32_t)l[2] | ((uint32_t)l[3] << 16),
                          (uint32_t)l[4] | ((uint32_t)l[5] << 16),
                          (uint32_t)l[6] | ((uint32_t)l[7] << 16));
    *(uint4*)((char*)g_xh + i * 2) = ph;
    *(uint4*)((char*)g_xl + i * 2) = pl;
}

// transpose + split: src [E][K][N] fp32 -> dh/dl [E][N][K] bf16
__global__ __launch_bounds__(256) void transpose_split_kernel(
    const float* __restrict__ src,
    __nv_bfloat16* __restrict__ dh,
    __nv_bfloat16* __restrict__ dl,
    int K, int N)
{
    __shared__ float ts[32][33];
    int e = blockIdx.z;
    size_t base = (size_t)e * K * N;
    int n0 = blockIdx.x * 32, k0 = blockIdx.y * 32;
    int tx = threadIdx.x & 31, ty = threadIdx.x >> 5;
    #pragma unroll
    for (int r = 0; r < 4; r++) {
        int k = k0 + ty + 8 * r;
        ts[ty + 8 * r][tx] = src[base + (size_t)k * N + n0 + tx];
    }
    __syncthreads();
    #pragma unroll
    for (int r = 0; r < 4; r++) {
        int n = n0 + ty + 8 * r;
        float v = ts[tx][ty + 8 * r];
        uint16_t h, l;
        bf16_split(v, h, l);
        size_t o = base + (size_t)n * K + k0 + tx;
        *(uint16_t*)(dh + o) = h;
        *(uint16_t*)(dl + o) = l;
    }
}

// =============== GEMM1 ===============
#define G1_OFF_TMEM 0
#define G1_OFF_MBAR 16      // mma mbars at +0,+8 ; tma-full mbars at +16,+24
#define G1_OFF_SLOT 64
#define G1_OFF_AH   1024
#define G1_OFF_AL   (G1_OFF_AH  + 2*16384)
#define G1_OFF_B1H  (G1_OFF_AL  + 2*16384)
#define G1_OFF_B1L  (G1_OFF_B1H + 2*16384)
#define G1_OFF_B3H  (G1_OFF_B1L + 2*16384)
#define G1_OFF_B3L  (G1_OFF_B3H + 2*16384)
#define G1_SMEM     (G1_OFF_B3L + 2*16384)

__global__ __launch_bounds__(256) void expert_up_mma(
    const float* __restrict__ x,
    const float* __restrict__ W1,
    const float* __restrict__ W3,
    const __grid_constant__ CUtensorMap tm_b1h,
    const __grid_constant__ CUtensorMap tm_b1l,
    const __grid_constant__ CUtensorMap tm_b3h,
    const __grid_constant__ CUtensorMap tm_b3l)
{
#if HAS_TCGEN05
    extern __shared__ char smem[];
    int e   = blockIdx.z;
    int cnt = g_count[e];
    int m0  = blockIdx.y * BM;
    if (m0 >= cnt) return;
    int n0  = blockIdx.x * BN1;

    uint32_t sb = smem_u32(smem);
    int tid = threadIdx.x, wid = tid >> 5, lane = tid & 31;
    int* sslot = (int*)(smem + G1_OFF_SLOT);
    if (tid < BM) { int r = m0 + tid; sslot[tid] = (r < cnt) ? g_list[e][r] : -1; }
    if (tid == 0) {
        mbar_init(sb + G1_OFF_MBAR, 1);      mbar_init(sb + G1_OFF_MBAR + 8, 1);
        mbar_init(sb + G1_OFF_MBAR + 16, 1); mbar_init(sb + G1_OFF_MBAR + 24, 1);
    }
    if (wid == 0) tmem_alloc(sb + G1_OFF_TMEM, 256);
    __syncthreads();
    uint32_t tb;
    asm volatile("ld.shared.b32 %0, [%1];" : "=r"(tb) : "r"(sb + G1_OFF_TMEM));

    int mph0 = 0, mph1 = 0;      // mma mbar phases (all threads)
    int fph0 = 0, fph1 = 0;      // tma full phases (tid0 only)
    for (int kc = 0; kc < NC1; kc++) {
        int s = kc & 1;
        int k0 = kc * BK;
        if (kc >= 2) {
            if (s == 0) { mbar_wait(sb + G1_OFF_MBAR, mph0); mph0 ^= 1; }
            else        { mbar_wait(sb + G1_OFF_MBAR + 8, mph1); mph1 ^= 1; }
        }
        // B via TMA (tid0)
        if (tid == 0) {
            uint32_t full = sb + G1_OFF_MBAR + 16 + 8 * s;
            mbar_expect_tx(full, 4 * 16384);
            int yy = e * F + n0;
            tma_2d(sb + G1_OFF_B1H + s * 16384, &tm_b1h, k0, yy, full);
            tma_2d(sb + G1_OFF_B1L + s * 16384, &tm_b1l, k0, yy, full);
            tma_2d(sb + G1_OFF_B3H + s * 16384, &tm_b3h, k0, yy, full);
            tma_2d(sb + G1_OFF_B3L + s * 16384, &tm_b3l, k0, yy, full);
        }
        // A via SIMT gather
        char* AoH = smem + G1_OFF_AH + s * 16384;
        char* AoL = smem + G1_OFF_AL + s * 16384;
        #pragma unroll
        for (int i = 0; i < 4; i++) {
            int id = tid + 256 * i;
            int row = id >> 3, c8 = id & 7;
            int slot = sslot[row];
            uint4 vh = make_uint4(0, 0, 0, 0), vl = vh;
            if (slot >= 0) {
                size_t o = (size_t)(slot >> 1) * H + k0 + c8 * 8;
                vh = *(const uint4*)(g_xh + o);
                vl = *(const uint4*)(g_xl + o);
            }
            uint32_t so = swz128(row * 128 + c8 * 16);
            *(uint4*)(AoH + so) = vh;
            *(uint4*)(AoL + so) = vl;
        }
        fence_async_shared();
        __syncthreads();
        if (tid == 0) {
            uint32_t full = sb + G1_OFF_MBAR + 16 + 8 * s;
            if (s == 0) { mbar_wait(full, fph0); fph0 ^= 1; }
            else        { mbar_wait(full, fph1); fph1 ^= 1; }
            uint64_t adh = make_desc(sb + G1_OFF_AH  + s * 16384);
            uint64_t adl = make_desc(sb + G1_OFF_AL  + s * 16384);
            uint64_t b1h = make_desc(sb + G1_OFF_B1H + s * 16384);
            uint64_t b1l = make_desc(sb + G1_OFF_B1L + s * 16384);
            uint64_t b3h = make_desc(sb + G1_OFF_B3H + s * 16384);
            uint64_t b3l = make_desc(sb + G1_OFF_B3L + s * 16384);
            #pragma unroll
            for (int ks = 0; ks < 4; ks++) {
                uint32_t en0 = (kc == 0 && ks == 0) ? 0u : 1u;
                uint64_t o = ks * 2;
                mma_bf16_ss(tb,       adh + o, b1h + o, IDESC_N(BN1), en0);
                mma_bf16_ss(tb,       adl + o, b1h + o, IDESC_N(BN1), 1u);
                mma_bf16_ss(tb,       adh + o, b1l + o, IDESC_N(BN1), 1u);
                mma_bf16_ss(tb + 128, adh + o, b3h + o, IDESC_N(BN1), en0);
                mma_bf16_ss(tb + 128, adl + o, b3h + o, IDESC_N(BN1), 1u);
                mma_bf16_ss(tb + 128, adh + o, b3l + o, IDESC_N(BN1), 1u);
            }
            mma_commit(sb + G1_OFF_MBAR + 8 * s);
        }
    }
    {
        int sl = (NC1 - 1) & 1;
        if (sl == 0) mbar_wait(sb + G1_OFF_MBAR, mph0);
        else         mbar_wait(sb + G1_OFF_MBAR + 8, mph1);
    }
    fence_tc_after();

    if (wid < 4) {
        int m = wid * 32 + lane;
        int slot = sslot[m];
        #pragma unroll
        for (int cb = 0; cb < 4; cb++) {
            uint32_t r1[32], r3[32];
            ldtm_x32(r1, tb + cb * 32);
            ldtm_x32(r3, tb + 128 + cb * 32);
            tmem_wait_ld();
            if (slot >= 0) {
                char* dh = (char*)(g_hmh + (size_t)slot * F + n0 + cb * 32);
                char* dl = (char*)(g_hml + (size_t)slot * F + n0 + cb * 32);
                #pragma unroll
                for (int c = 0; c < 32; c += 2) {
                    float g0 = __uint_as_float(r1[c]),     u0 = __uint_as_float(r3[c]);
                    float g1 = __uint_as_float(r1[c + 1]), u1 = __uint_as_float(r3[c + 1]);
                    float v0 = (g0 / (1.f + expf(-g0))) * u0;
                    float v1 = (g1 / (1.f + expf(-g1))) * u1;
                    uint16_t h0, l0, h1, l1;
                    bf16_split(v0, h0, l0);
                    bf16_split(v1, h1, l1);
                    *(uint32_t*)(dh + c * 2) = (uint32_t)h0 | ((uint32_t)h1 << 16);
                    *(uint32_t*)(dl + c * 2) = (uint32_t)l0 | ((uint32_t)l1 << 16);
                }
            }
        }
    }
    __syncthreads();
    if (wid == 0) tmem_dealloc(tb, 256);
#else
    // ---------- SIMT fallback ----------
    int e   = blockIdx.z;
    int cnt = g_count[e];
    int m0  = blockIdx.y * BM;
    if (m0 >= cnt) return;

    __shared__ float Xs[BM][33];
    __shared__ float B1s[32][64];
    __shared__ float B3s[32][64];
    __shared__ int   stok[BM];
    __shared__ int   sslot[BM];

    int tid = threadIdx.x;
    for (int i = tid; i < BM; i += 256) {
        int r = m0 + i;
        int slot = (r < cnt) ? g_list[e][r] : -1;
        sslot[i] = slot;
        stok[i]  = (slot >= 0) ? (slot >> 1) : -1;
    }
    __syncthreads();

    const float* w1p = W1 + (size_t)e * H * F;
    const float* w3p = W3 + (size_t)e * H * F;
    int tx = tid & 15, ty = tid >> 4;

    for (int half = 0; half < 2; half++) {
        int n0 = blockIdx.x * BN1 + half * 64;
        float acc1[8][4], acc3[8][4];
        #pragma unroll
        for (int i = 0; i < 8; i++)
            #pragma unroll
            for (int j = 0; j < 4; j++) { acc1[i][j] = 0.f; acc3[i][j] = 0.f; }

        for (int k0 = 0; k0 < H; k0 += 32) {
            __syncthreads();
            for (int i = tid; i < BM * 32; i += 256) {
                int m = i >> 5, k = i & 31;
                int tok = stok[m];
                Xs[m][k] = (tok >= 0) ? x[(size_t)tok * H + k0 + k] : 0.f;
            }
            for (int i = tid; i < 32 * 64; i += 256) {
                int k = i >> 6, n = i & 63;
                size_t off = (size_t)(k0 + k) * F + n0 + n;
                B1s[k][n] = w1p[off];
                B3s[k][n] = w3p[off];
            }
            __syncthreads();
            #pragma unroll
            for (int kk = 0; kk < 32; kk++) {
                float a[8], b1[4], b3[4];
                #pragma unroll
                for (int i = 0; i < 8; i++) a[i] = Xs[ty + 16 * i][kk];
                #pragma unroll
                for (int j = 0; j < 4; j++) { b1[j] = B1s[kk][tx + 16 * j]; b3[j] = B3s[kk][tx + 16 * j]; }
                #pragma unroll
                for (int i = 0; i < 8; i++)
                    #pragma unroll
                    for (int j = 0; j < 4; j++) {
                        acc1[i][j] += a[i] * b1[j];
                        acc3[i][j] += a[i] * b3[j];
                    }
            }
        }
        #pragma unroll
        for (int i = 0; i < 8; i++) {
            int m = ty + 16 * i;
            int slot = sslot[m];
            if (slot < 0) continue;
            float* dst = g_hmid + (size_t)slot * F + n0;
            #pragma unroll
            for (int j = 0; j < 4; j++) {
                float g = acc1[i][j];
                float u = acc3[i][j];
                float sg = g / (1.f + expf(-g));
                dst[tx + 16 * j] = sg * u;
            }
        }
        __syncthreads();
    }
#endif
}

// =============== GEMM2 ===============
#define G2_OFF_TMEM 0
#define G2_OFF_MBAR 16
#define G2_OFF_SLOT 64
#define G2_OFF_AH   1024
#define G2_OFF_AL   (G2_OFF_AH + 2*16384)
#define G2_OFF_BH   (G2_OFF_AL + 2*16384)
#define G2_OFF_BL   (G2_OFF_BH + 2*16384)
#define G2_SMEM     (G2_OFF_BL + 2*16384)

__global__ __launch_bounds__(256) void expert_down_mma(
    const float* __restrict__ W2,
    const __grid_constant__ CUtensorMap tm_b2h,
    const __grid_constant__ CUtensorMap tm_b2l)
{
#if HAS_TCGEN05
    extern __shared__ char smem[];
    int e   = blockIdx.z;
    int cnt = g_count[e];
    int m0  = blockIdx.y * BM;
    if (m0 >= cnt) return;
    int n0  = blockIdx.x * BN2;

    uint32_t sb = smem_u32(smem);
    int tid = threadIdx.x, wid = tid >> 5, lane = tid & 31;
    int* sslot = (int*)(smem + G2_OFF_SLOT);
    if (tid < BM) { int r = m0 + tid; sslot[tid] = (r < cnt) ? g_list[e][r] : -1; }
    if (tid == 0) {
        mbar_init(sb + G2_OFF_MBAR, 1);      mbar_init(sb + G2_OFF_MBAR + 8, 1);
        mbar_init(sb + G2_OFF_MBAR + 16, 1); mbar_init(sb + G2_OFF_MBAR + 24, 1);
    }
    if (wid == 0) tmem_alloc(sb + G2_OFF_TMEM, 128);
    __syncthreads();
    uint32_t tb;
    asm volatile("ld.shared.b32 %0, [%1];" : "=r"(tb) : "r"(sb + G2_OFF_TMEM));

    int mph0 = 0, mph1 = 0;
    int fph0 = 0, fph1 = 0;
    for (int kc = 0; kc < NC2; kc++) {
        int s = kc & 1;
        int k0 = kc * BK;
        if (kc >= 2) {
            if (s == 0) { mbar_wait(sb + G2_OFF_MBAR, mph0); mph0 ^= 1; }
            else        { mbar_wait(sb + G2_OFF_MBAR + 8, mph1); mph1 ^= 1; }
        }
        if (tid == 0) {
            uint32_t full = sb + G2_OFF_MBAR + 16 + 8 * s;
            mbar_expect_tx(full, 2 * 16384);
            int yy = e * H + n0;
            tma_2d(sb + G2_OFF_BH + s * 16384, &tm_b2h, k0, yy, full);
            tma_2d(sb + G2_OFF_BL + s * 16384, &tm_b2l, k0, yy, full);
        }
        char* AoH = smem + G2_OFF_AH + s * 16384;
        char* AoL = smem + G2_OFF_AL + s * 16384;
        #pragma unroll
        for (int i = 0; i < 4; i++) {
            int id = tid + 256 * i;
            int row = id >> 3, c8 = id & 7;
            int slot = sslot[row];
            uint4 vh = make_uint4(0, 0, 0, 0), vl = vh;
            if (slot >= 0) {
                size_t o = (size_t)slot * F + k0 + c8 * 8;
                vh = *(const uint4*)(g_hmh + o);
                vl = *(const uint4*)(g_hml + o);
            }
            uint32_t so = swz128(row * 128 + c8 * 16);
            *(uint4*)(AoH + so) = vh;
            *(uint4*)(AoL + so) = vl;
        }
        fence_async_shared();
        __syncthreads();
        if (tid == 0) {
            uint32_t full = sb + G2_OFF_MBAR + 16 + 8 * s;
            if (s == 0) { mbar_wait(full, fph0); fph0 ^= 1; }
            else        { mbar_wait(full, fph1); fph1 ^= 1; }
            uint64_t adh = make_desc(sb + G2_OFF_AH + s * 16384);
            uint64_t adl = make_desc(sb + G2_OFF_AL + s * 16384);
            uint64_t bdh = make_desc(sb + G2_OFF_BH + s * 16384);
            uint64_t bdl = make_desc(sb + G2_OFF_BL + s * 16384);
            #pragma unroll
            for (int ks = 0; ks < 4; ks++) {
                uint32_t en0 = (kc == 0 && ks == 0) ? 0u : 1u;
                uint64_t o = ks * 2;
                mma_bf16_ss(tb, adh + o, bdh + o, IDESC_N(BN2), en0);
                mma_bf16_ss(tb, adl + o, bdh + o, IDESC_N(BN2), 1u);
                mma_bf16_ss(tb, adh + o, bdl + o, IDESC_N(BN2), 1u);
            }
            mma_commit(sb + G2_OFF_MBAR + 8 * s);
        }
    }
    {
        int sl = (NC2 - 1) & 1;
        if (sl == 0) mbar_wait(sb + G2_OFF_MBAR, mph0);
        else         mbar_wait(sb + G2_OFF_MBAR + 8, mph1);
    }
    fence_tc_after();

    if (wid < 4) {
        int m = wid * 32 + lane;
        int slot = sslot[m];
        float gw = (slot >= 0) ? g_wslot[slot] : 0.f;
        #pragma unroll
        for (int cb = 0; cb < 4; cb++) {
            uint32_t r0[32];
            ldtm_x32(r0, tb + cb * 32);
            tmem_wait_ld();
            if (slot >= 0) {
                float* dst = g_outpair + (size_t)slot * H + n0 + cb * 32;
                #pragma unroll
                for (int c = 0; c < 32; c += 4) {
                    float4 o;
                    #pragma unroll
                    for (int j = 0; j < 4; j++) (&o.x)[j] = gw * __uint_as_float(r0[c + j]);
                    *(float4*)(dst + c) = o;
                }
            }
        }
    }
    __syncthreads();
    if (wid == 0) tmem_dealloc(tb, 128);
#else
    // ---------- SIMT fallback ----------
    int e   = blockIdx.z;
    int cnt = g_count[e];
    int m0  = blockIdx.y * BM;
    if (m0 >= cnt) return;

    __shared__ float As[BM][33];
    __shared__ float Bs[32][64];
    __shared__ int   sslot[BM];

    int tid = threadIdx.x;
    for (int i = tid; i < BM; i += 256) {
        int r = m0 + i;
        sslot[i] = (r < cnt) ? g_list[e][r] : -1;
    }
    __syncthreads();

    const float* w2p = W2 + (size_t)e * F * H;
    int tx = tid & 15, ty = tid >> 4;

    for (int half = 0; half < 2; half++) {
        int n0 = blockIdx.x * BN2 + half * 64;
        float acc[8][4];
        #pragma unroll
        for (int i = 0; i < 8; i++)
            #pragma unroll
            for (int j = 0; j < 4; j++) acc[i][j] = 0.f;

        for (int k0 = 0; k0 < F; k0 += 32) {
            __syncthreads();
            for (int i = tid; i < BM * 32; i += 256) {
                int m = i >> 5, k = i & 31;
                int slot = sslot[m];
                As[m][k] = (slot >= 0) ? g_hmid[(size_t)slot * F + k0 + k] : 0.f;
            }
            for (int i = tid; i < 32 * 64; i += 256) {
                int k = i >> 6, n = i & 63;
                Bs[k][n] = w2p[(size_t)(k0 + k) * H + n0 + n];
            }
            __syncthreads();
            #pragma unroll
            for (int kk = 0; kk < 32; kk++) {
                float a[8], b[4];
                #pragma unroll
                for (int i = 0; i < 8; i++) a[i] = As[ty + 16 * i][kk];
                #pragma unroll
                for (int j = 0; j < 4; j++) b[j] = Bs[kk][tx + 16 * j];
                #pragma unroll
                for (int i = 0; i < 8; i++)
                    #pragma unroll
                    for (int j = 0; j < 4; j++) acc[i][j] += a[i] * b[j];
            }
        }
        #pragma unroll
        for (int i = 0; i < 8; i++) {
            int m = ty + 16 * i;
            int slot = sslot[m];
            if (slot < 0) continue;
            float gw = g_wslot[slot];
            float* dst = g_outpair + (size_t)slot * H + n0;
            #pragma unroll
            for (int j = 0; j < 4; j++) dst[tx + 16 * j] = gw * acc[i][j];
        }
        __syncthreads();
    }
#endif
}

__global__ __launch_bounds__(256) void combine_kernel(float* __restrict__ out)
{
    int i = blockIdx.x * 256 + threadIdx.x;
    if (i >= T * H) return;
    int t = i >> 10;
    int h = i & (H - 1);
    out[i] = g_outpair[(size_t)(2 * t) * H + h] + g_outpair[(size_t)(2 * t + 1) * H + h];
}

// =============== host: tensor-map encode via driver entry point ===============
typedef CUresult (*PFN_cuTensorMapEncodeTiled)(
    CUtensorMap*, CUtensorMapDataType, cuuint32_t, void*,
    const cuuint64_t*, const cuuint64_t*, const cuuint32_t*, const cuuint32_t*,
    CUtensorMapInterleave, CUtensorMapSwizzle, CUtensorMapL2promotion,
    CUtensorMapFloatOOBfill);

static PFN_cuTensorMapEncodeTiled get_encoder() {
    void* fn = nullptr;
    cudaDriverEntryPointQueryResult st;
    cudaGetDriverEntryPoint("cuTensorMapEncodeTiled", &fn, cudaEnableDefault, &st);
    return (PFN_cuTensorMapEncodeTiled)fn;
}

static void encode_2d(PFN_cuTensorMapEncodeTiled enc, CUtensorMap* tm, void* ptr,
                      uint64_t d0, uint64_t d1, uint32_t b0, uint32_t b1) {
    cuuint64_t dims[2] = {d0, d1};
    cuuint64_t strides[1] = {d0 * 2};   // bf16
    cuuint32_t box[2] = {b0, b1};
    cuuint32_t es[2] = {1, 1};
    enc(tm, CU_TENSOR_MAP_DATA_TYPE_BFLOAT16, 2, ptr, dims, strides, box, es,
        CU_TENSOR_MAP_INTERLEAVE_NONE, CU_TENSOR_MAP_SWIZZLE_128B,
        CU_TENSOR_MAP_L2_PROMOTION_L2_128B, CU_TENSOR_MAP_FLOAT_OOB_FILL_NONE);
}

extern "C" void kernel_launch(void* const* d_in, const int* in_sizes, int n_in,
                              void* d_out, int out_size)
{
    const float* x  = (const float*)d_in[0];
    const float* Wr = (const float*)d_in[1];
    const float* W1 = (const float*)d_in[2];
    const float* W2 = (const float*)d_in[3];
    const float* W3 = (const float*)d_in[4];
    float* out = (float*)d_out;

    __nv_bfloat16 *w1h, *w1l, *w3h, *w3l, *w2h, *w2l;
    cudaGetSymbolAddress((void**)&w1h, g_w1h);
    cudaGetSymbolAddress((void**)&w1l, g_w1l);
    cudaGetSymbolAddress((void**)&w3h, g_w3h);
    cudaGetSymbolAddress((void**)&w3l, g_w3l);
    cudaGetSymbolAddress((void**)&w2h, g_w2h);
    cudaGetSymbolAddress((void**)&w2l, g_w2l);

    PFN_cuTensorMapEncodeTiled enc = get_encoder();
    CUtensorMap tm_b1h, tm_b1l, tm_b3h, tm_b3l, tm_b2h, tm_b2l;
    if (enc) {
        encode_2d(enc, &tm_b1h, w1h, H, (uint64_t)E * F, BK, BN1);
        encode_2d(enc, &tm_b1l, w1l, H, (uint64_t)E * F, BK, BN1);
        encode_2d(enc, &tm_b3h, w3h, H, (uint64_t)E * F, BK, BN1);
        encode_2d(enc, &tm_b3l, w3l, H, (uint64_t)E * F, BK, BN1);
        encode_2d(enc, &tm_b2h, w2h, F, (uint64_t)E * H, BK, BN2);
        encode_2d(enc, &tm_b2l, w2l, F, (uint64_t)E * H, BK, BN2);
    }

    cudaFuncSetAttribute(expert_up_mma,   cudaFuncAttributeMaxDynamicSharedMemorySize, G1_SMEM);
    cudaFuncSetAttribute(expert_down_mma, cudaFuncAttributeMaxDynamicSharedMemorySize, G2_SMEM);

    zero_counts_kernel<<<1, 32>>>();
    router_kernel<<<T, 256>>>(x, Wr);

    convert_x_kernel<<<(T * H) / (256 * 8), 256>>>(x);
    {
        dim3 gw13(F / 32, H / 32, E);
        transpose_split_kernel<<<gw13, 256>>>(W1, w1h, w1l, H, F);
        transpose_split_kernel<<<gw13, 256>>>(W3, w3h, w3l, H, F);
        dim3 gw2(H / 32, F / 32, E);
        transpose_split_kernel<<<gw2, 256>>>(W2, w2h, w2l, F, H);
    }

    dim3 g1(F / BN1, MT_MAX, E);
    expert_up_mma<<<g1, 256, G1_SMEM>>>(x, W1, W3, tm_b1h, tm_b1l, tm_b3h, tm_b3l);

    dim3 g2(H / BN2, MT_MAX, E);
    expert_down_mma<<<g2, 256, G2_SMEM>>>(W2, tm_b2h, tm_b2l);

    combine_kernel<<<(T * H + 255) / 256, 256>>>(out);
}

// round 11
// speedup vs baseline: 6.7166x; 1.7961x over previous
#include <cuda_runtime.h>
#include <cuda.h>
#include <cuda_bf16.h>
#include <cstdint>
#include <math.h>

#define H 1024
#define F 4096
#define E 8
#define T 2048
#define SLOTS (2*T)

#define BM 128
#define BN1 128
#define BN2 128
#define BK 64
#define NC1 (H/BK)     // 16
#define NC2 (F/BK)     // 64
#define MT_MAX (T/BM)  // 16

#if defined(__CUDA_ARCH_FEAT_SM103_ALL) || defined(__CUDA_ARCH_FEAT_SM100_ALL) || \
    (defined(__CUDA_ARCH_SPECIFIC__) && (__CUDA_ARCH_SPECIFIC__ == 1030)) || \
    (defined(__CUDA_ARCH_FAMILY_SPECIFIC__) && (__CUDA_ARCH_FAMILY_SPECIFIC__ == 1030))
#define HAS_TCGEN05 1
#else
#define HAS_TCGEN05 0
#endif

__device__ int   g_count[E];
__device__ int   g_off[E + 1];
__device__ int   g_list[E][T];
__device__ int   g_rowslot[SLOTS];
__device__ __align__(1024) float g_wslot[SLOTS];
__device__ __align__(1024) float g_hmid[(size_t)SLOTS * F];      // SIMT fallback only
__device__ __align__(1024) float g_outpair[(size_t)SLOTS * H];

__device__ __align__(1024) __nv_bfloat16 g_xh[(size_t)T * H];
__device__ __align__(1024) __nv_bfloat16 g_xl[(size_t)T * H];
__device__ __align__(1024) __nv_bfloat16 g_xgh[(size_t)SLOTS * H];
__device__ __align__(1024) __nv_bfloat16 g_xgl[(size_t)SLOTS * H];
__device__ __align__(1024) __nv_bfloat16 g_w1h[(size_t)E*F*H];
__device__ __align__(1024) __nv_bfloat16 g_w1l[(size_t)E*F*H];
__device__ __align__(1024) __nv_bfloat16 g_w3h[(size_t)E*F*H];
__device__ __align__(1024) __nv_bfloat16 g_w3l[(size_t)E*F*H];
__device__ __align__(1024) __nv_bfloat16 g_w2h[(size_t)E*H*F];
__device__ __align__(1024) __nv_bfloat16 g_w2l[(size_t)E*H*F];
__device__ __align__(1024) __nv_bfloat16 g_hmh[(size_t)SLOTS*F];
__device__ __align__(1024) __nv_bfloat16 g_hml[(size_t)SLOTS*F];

__device__ __forceinline__ uint32_t smem_u32(const void* p) {
    uint32_t a;
    asm("{ .reg .u64 t; cvta.to.shared.u64 t, %1; cvt.u32.u64 %0, t; }" : "=r"(a) : "l"(p));
    return a;
}

__device__ __forceinline__ void bf16_split(float v, uint16_t& hi, uint16_t& lo) {
    __nv_bfloat16 h = __float2bfloat16(v);
    __nv_bfloat16 l = __float2bfloat16(v - __bfloat162float(h));
    hi = __bfloat16_as_ushort(h);
    lo = __bfloat16_as_ushort(l);
}

#if HAS_TCGEN05
static __device__ __forceinline__ uint64_t make_desc(uint32_t addr) {
    const uint64_t base = (uint64_t(2) << 61) | (uint64_t(1) << 46) |
                          (uint64_t(64) << 32) | (uint64_t(1) << 16);
    return base | ((uint64_t)(addr >> 4) & 0x3FFF);
}

#define IDESC_N(N) ((1u << 4) | (1u << 7) | (1u << 10) | (((N) / 8) << 17) | ((BM / 16) << 24))

__device__ __forceinline__ void mma_bf16_ss(uint32_t d, uint64_t ad, uint64_t bd,
                                            uint32_t idesc, uint32_t en) {
    asm volatile(
        "{\n\t.reg .pred p;\n\t"
        "setp.ne.u32 p, %4, 0;\n\t"
        "tcgen05.mma.cta_group::1.kind::f16 [%0], %1, %2, %3, {%5,%5,%5,%5}, p;\n\t}"
        :: "r"(d), "l"(ad), "l"(bd), "r"(idesc), "r"(en), "r"(0u) : "memory");
}
__device__ __forceinline__ void tmem_alloc(uint32_t smem_dst, uint32_t ncols) {
    asm volatile("tcgen05.alloc.cta_group::1.sync.aligned.shared::cta.b32 [%0], %1;"
                 :: "r"(smem_dst), "r"(ncols) : "memory");
}
__device__ __forceinline__ void tmem_dealloc(uint32_t tb, uint32_t ncols) {
    asm volatile("tcgen05.relinquish_alloc_permit.cta_group::1.sync.aligned;");
    asm volatile("tcgen05.dealloc.cta_group::1.sync.aligned.b32 %0, %1;" :: "r"(tb), "r"(ncols));
}
__device__ __forceinline__ void mma_commit(uint32_t mbar) {
    asm volatile("tcgen05.commit.cta_group::1.mbarrier::arrive::one.shared::cluster.b64 [%0];"
                 :: "r"(mbar) : "memory");
}
__device__ __forceinline__ void mbar_init(uint32_t mbar, uint32_t cnt) {
    asm volatile("mbarrier.init.shared.b64 [%0], %1;" :: "r"(mbar), "r"(cnt) : "memory");
}
__device__ __forceinline__ void mbar_wait(uint32_t mbar, uint32_t parity) {
    uint32_t done;
    asm volatile(
        "{\n\t.reg .pred p;\n\t"
        "mbarrier.try_wait.parity.acquire.cta.shared::cta.b64 p, [%1], %2;\n\t"
        "selp.b32 %0, 1, 0, p;\n\t}"
        : "=r"(done) : "r"(mbar), "r"(parity) : "memory");
    if (!done) {
        asm volatile(
            "{\n\t.reg .pred P1;\n\t"
            "W_%=:\n\t"
            "mbarrier.try_wait.parity.acquire.cta.shared::cta.b64 P1, [%0], %1, 0x989680;\n\t"
            "@P1 bra.uni D_%=;\n\t"
            "bra.uni W_%=;\n\t"
            "D_%=:\n\t}"
            :: "r"(mbar), "r"(parity) : "memory");
    }
}
__device__ __forceinline__ void mbar_expect_tx(uint32_t mbar, uint32_t bytes) {
    asm volatile("mbarrier.arrive.expect_tx.shared.b64 _, [%0], %1;"
                 :: "r"(mbar), "r"(bytes) : "memory");
}
__device__ __forceinline__ void tma_2d(uint32_t dst, const CUtensorMap* map,
                                       int x, int y, uint32_t mbar) {
    asm volatile(
        "cp.async.bulk.tensor.2d.shared::cta.global.tile.mbarrier::complete_tx::bytes "
        "[%0], [%1, {%2, %3}], [%4];"
        :: "r"(dst), "l"(map), "r"(x), "r"(y), "r"(mbar) : "memory");
}
__device__ __forceinline__ void fence_tc_after() {
    asm volatile("tcgen05.fence::after_thread_sync;" ::: "memory");
}
__device__ __forceinline__ void ldtm_x32(uint32_t* r, uint32_t a) {
    asm volatile(
        "tcgen05.ld.sync.aligned.32x32b.x32.b32 "
        "{%0,%1,%2,%3,%4,%5,%6,%7,%8,%9,%10,%11,%12,%13,%14,%15,"
        "%16,%17,%18,%19,%20,%21,%22,%23,%24,%25,%26,%27,%28,%29,%30,%31}, [%32];"
        : "=r"(r[0]), "=r"(r[1]), "=r"(r[2]), "=r"(r[3]), "=r"(r[4]), "=r"(r[5]),
          "=r"(r[6]), "=r"(r[7]), "=r"(r[8]), "=r"(r[9]), "=r"(r[10]), "=r"(r[11]),
          "=r"(r[12]), "=r"(r[13]), "=r"(r[14]), "=r"(r[15]), "=r"(r[16]), "=r"(r[17]),
          "=r"(r[18]), "=r"(r[19]), "=r"(r[20]), "=r"(r[21]), "=r"(r[22]), "=r"(r[23]),
          "=r"(r[24]), "=r"(r[25]), "=r"(r[26]), "=r"(r[27]), "=r"(r[28]), "=r"(r[29]),
          "=r"(r[30]), "=r"(r[31])
        : "r"(a));
}
__device__ __forceinline__ void tmem_wait_ld() {
    asm volatile("tcgen05.wait::ld.sync.aligned;" ::: "memory");
}
#endif // HAS_TCGEN05

// =============== prep kernels ===============
__global__ void zero_counts_kernel() {
    if (threadIdx.x < E) g_count[threadIdx.x] = 0;
}

__global__ __launch_bounds__(256) void router_kernel(
    const float* __restrict__ x, const float* __restrict__ Wr)
{
    int t = blockIdx.x;
    __shared__ float xs[H];
    __shared__ float logits[E];
    int tid = threadIdx.x;
    for (int i = tid; i < H; i += 256) xs[i] = x[(size_t)t * H + i];
    __syncthreads();
    int w = tid >> 5, lane = tid & 31;
    {
        const float* wr = Wr + w * H;
        float s = 0.f;
        for (int i = lane; i < H; i += 32) s += xs[i] * wr[i];
        #pragma unroll
        for (int off = 16; off; off >>= 1) s += __shfl_xor_sync(0xffffffffu, s, off);
        if (lane == 0) logits[w] = s;
    }
    __syncthreads();
    if (tid == 0) {
        int e0 = 0; float b0 = logits[0];
        #pragma unroll
        for (int e = 1; e < E; e++) if (logits[e] > b0) { b0 = logits[e]; e0 = e; }
        int e1 = -1; float b1 = -3.0e38f;
        #pragma unroll
        for (int e = 0; e < E; e++) if (e != e0 && logits[e] > b1) { b1 = logits[e]; e1 = e; }
        float w0 = 1.f / (1.f + expf(b1 - b0));
        float w1 = 1.f - w0;
        int p0 = atomicAdd(&g_count[e0], 1);
        int p1 = atomicAdd(&g_count[e1], 1);
        g_list[e0][p0] = 2 * t;
        g_list[e1][p1] = 2 * t + 1;
        g_wslot[2 * t]     = w0;
        g_wslot[2 * t + 1] = w1;
    }
}

__global__ void finalize_router_kernel() {
    int o = 0;
    #pragma unroll
    for (int e = 0; e < E; e++) { g_off[e] = o; o += g_count[e]; }
    g_off[E] = o;
}

__global__ __launch_bounds__(256) void convert_x_kernel(const float* __restrict__ x)
{
    size_t i = ((size_t)blockIdx.x * 256 + threadIdx.x) * 8;
    float v[8];
    *(float4*)(v)     = *(const float4*)(x + i);
    *(float4*)(v + 4) = *(const float4*)(x + i + 4);
    uint16_t h[8], l[8];
    #pragma unroll
    for (int j = 0; j < 8; j++) bf16_split(v[j], h[j], l[j]);
    uint4 ph = make_uint4((uint32_t)h[0] | ((uint32_t)h[1] << 16),
                          (uint32_t)h[2] | ((uint32_t)h[3] << 16),
                          (uint32_t)h[4] | ((uint32_t)h[5] << 16),
                          (uint32_t)h[6] | ((uint32_t)h[7] << 16));
    uint4 pl = make_uint4((uint32_t)l[0] | ((uint32_t)l[1] << 16),
                          (uint32_t)l[2] | ((uint32_t)l[3] << 16),
                          (uint32_t)l[4] | ((uint32_t)l[5] << 16),
                          (uint32_t)l[6] | ((uint32_t)l[7] << 16));
    *(uint4*)((char*)g_xh + i * 2) = ph;
    *(uint4*)((char*)g_xl + i * 2) = pl;
}

// gather tokens into contiguous per-expert row order
__global__ __launch_bounds__(256) void gather_x_kernel()
{
    int r = blockIdx.x;    // 0..SLOTS-1
    int e = 0;
    while (e < E - 1 && r >= g_off[e + 1]) e++;
    int p = r - g_off[e];
    int slot = g_list[e][p];
    if (threadIdx.x == 0) g_rowslot[r] = slot;
    size_t so = (size_t)(slot >> 1) * H;
    size_t dof = (size_t)r * H;
    ((uint2*)(g_xgh + dof))[threadIdx.x] = ((const uint2*)(g_xh + so))[threadIdx.x];
    ((uint2*)(g_xgl + dof))[threadIdx.x] = ((const uint2*)(g_xl + so))[threadIdx.x];
}

// transpose + split: src [E][K][N] fp32 -> dh/dl [E][N][K] bf16
// FIXED: 4 elements/thread (256*4 = 1024 = 32*32), k index kg*4+j in [0,31],
// uint2 (8B) global stores. The R7 version wrote 8/thread -> shared OOB reads
// (ts[63][...]) + global OOB writes on the last k-tile -> illegal memory access.
__global__ __launch_bounds__(256) void transpose_split_kernel(
    const float* __restrict__ src,
    __nv_bfloat16* __restrict__ dh,
    __nv_bfloat16* __restrict__ dl,
    int K, int N)
{
    __shared__ float ts[32][33];
    int e = blockIdx.z;
    size_t base = (size_t)e * K * N;
    int n0 = blockIdx.x * 32, k0 = blockIdx.y * 32;
    int tx = threadIdx.x & 31, ty = threadIdx.x >> 5;
    #pragma unroll
    for (int r = 0; r < 4; r++) {
        int k = k0 + ty + 8 * r;
        ts[ty + 8 * r][tx] = src[base + (size_t)k * N + n0 + tx];
    }
    __syncthreads();
    int nl = threadIdx.x >> 3;   // 0..31  (n within tile)
    int kg = threadIdx.x & 7;    // 0..7   (group of 4 k's)
    uint16_t hv[4], lv[4];
    #pragma unroll
    for (int j = 0; j < 4; j++) {
        float v = ts[kg * 4 + j][nl];
        bf16_split(v, hv[j], lv[j]);
    }
    uint2 ph = make_uint2((uint32_t)hv[0] | ((uint32_t)hv[1] << 16),
                          (uint32_t)hv[2] | ((uint32_t)hv[3] << 16));
    uint2 pl = make_uint2((uint32_t)lv[0] | ((uint32_t)lv[1] << 16),
                          (uint32_t)lv[2] | ((uint32_t)lv[3] << 16));
    size_t o = base + (size_t)(n0 + nl) * K + k0 + kg * 4;
    *(uint2*)(dh + o) = ph;
    *(uint2*)(dl + o) = pl;
}

// =============== GEMM1: Xg @ (W1,W3)^T -> silu*up -> hm (row order) ===============
#define TILEB 16384
#define G1_OFF_TMEM 0
#define G1_FULL(s)  (16 + 8*(s))
#define G1_MDONE(s) (32 + 8*(s))
#define G1_OFF_AH   1024
#define G1_OFF_AL   (G1_OFF_AH  + 2*TILEB)
#define G1_OFF_B1H  (G1_OFF_AL  + 2*TILEB)
#define G1_OFF_B1L  (G1_OFF_B1H + 2*TILEB)
#define G1_OFF_B3H  (G1_OFF_B1L + 2*TILEB)
#define G1_OFF_B3L  (G1_OFF_B3H + 2*TILEB)
#define G1_SMEM     (G1_OFF_B3L + 2*TILEB)

__global__ __launch_bounds__(256) void expert_up_mma(
    const float* __restrict__ x,
    const float* __restrict__ W1,
    const float* __restrict__ W3,
    const __grid_constant__ CUtensorMap tm_ah,
    const __grid_constant__ CUtensorMap tm_al,
    const __grid_constant__ CUtensorMap tm_b1h,
    const __grid_constant__ CUtensorMap tm_b1l,
    const __grid_constant__ CUtensorMap tm_b3h,
    const __grid_constant__ CUtensorMap tm_b3l)
{
#if HAS_TCGEN05
    extern __shared__ char smem[];
    int e   = blockIdx.z;
    int cnt = g_count[e];
    int m0  = blockIdx.y * BM;
    if (m0 >= cnt) return;
    int n0  = blockIdx.x * BN1;
    int rowbase = g_off[e] + m0;

    uint32_t sb = smem_u32(smem);
    int tid = threadIdx.x, wid = tid >> 5, lane = tid & 31;
    if (tid == 0) {
        #pragma unroll
        for (int s = 0; s < 2; s++) { mbar_init(sb + G1_FULL(s), 1); mbar_init(sb + G1_MDONE(s), 1); }
    }
    if (wid == 0) tmem_alloc(sb + G1_OFF_TMEM, 256);
    __syncthreads();
    uint32_t tb;
    asm volatile("ld.shared.b32 %0, [%1];" : "=r"(tb) : "r"(sb + G1_OFF_TMEM));

    if (tid == 0) {
        int ywb = e * F + n0;
        #pragma unroll
        for (int p = 0; p < 2; p++) {
            uint32_t full = sb + G1_FULL(p);
            mbar_expect_tx(full, 6 * TILEB);
            int kk = p * BK;
            tma_2d(sb + G1_OFF_AH  + p * TILEB, &tm_ah,  kk, rowbase, full);
            tma_2d(sb + G1_OFF_AL  + p * TILEB, &tm_al,  kk, rowbase, full);
            tma_2d(sb + G1_OFF_B1H + p * TILEB, &tm_b1h, kk, ywb, full);
            tma_2d(sb + G1_OFF_B1L + p * TILEB, &tm_b1l, kk, ywb, full);
            tma_2d(sb + G1_OFF_B3H + p * TILEB, &tm_b3h, kk, ywb, full);
            tma_2d(sb + G1_OFF_B3L + p * TILEB, &tm_b3l, kk, ywb, full);
        }
        int fph[2] = {0, 0}, mph[2] = {0, 0};
        for (int kc = 0; kc < NC1; kc++) {
            int s = kc & 1;
            mbar_wait(sb + G1_FULL(s), fph[s]); fph[s] ^= 1;
            uint64_t adh = make_desc(sb + G1_OFF_AH  + s * TILEB);
            uint64_t adl = make_desc(sb + G1_OFF_AL  + s * TILEB);
            uint64_t b1h = make_desc(sb + G1_OFF_B1H + s * TILEB);
            uint64_t b1l = make_desc(sb + G1_OFF_B1L + s * TILEB);
            uint64_t b3h = make_desc(sb + G1_OFF_B3H + s * TILEB);
            uint64_t b3l = make_desc(sb + G1_OFF_B3L + s * TILEB);
            #pragma unroll
            for (int ks = 0; ks < 4; ks++) {
                uint32_t en0 = (kc == 0 && ks == 0) ? 0u : 1u;
                uint64_t o = ks * 2;
                mma_bf16_ss(tb,       adh + o, b1h + o, IDESC_N(BN1), en0);
                mma_bf16_ss(tb,       adl + o, b1h + o, IDESC_N(BN1), 1u);
                mma_bf16_ss(tb,       adh + o, b1l + o, IDESC_N(BN1), 1u);
                mma_bf16_ss(tb + 128, adh + o, b3h + o, IDESC_N(BN1), en0);
                mma_bf16_ss(tb + 128, adl + o, b3h + o, IDESC_N(BN1), 1u);
                mma_bf16_ss(tb + 128, adh + o, b3l + o, IDESC_N(BN1), 1u);
            }
            mma_commit(sb + G1_MDONE(s));
            // deferred refill: stage used at kc-1 gets chunk kc+1
            if (kc >= 1) {
                int pk = kc - 1, sp = pk & 1;
                mbar_wait(sb + G1_MDONE(sp), mph[sp]); mph[sp] ^= 1;
                if (pk + 2 < NC1) {
                    uint32_t full = sb + G1_FULL(sp);
                    mbar_expect_tx(full, 6 * TILEB);
                    int kk = (pk + 2) * BK;
                    tma_2d(sb + G1_OFF_AH  + sp * TILEB, &tm_ah,  kk, rowbase, full);
                    tma_2d(sb + G1_OFF_AL  + sp * TILEB, &tm_al,  kk, rowbase, full);
                    tma_2d(sb + G1_OFF_B1H + sp * TILEB, &tm_b1h, kk, ywb, full);
                    tma_2d(sb + G1_OFF_B1L + sp * TILEB, &tm_b1l, kk, ywb, full);
                    tma_2d(sb + G1_OFF_B3H + sp * TILEB, &tm_b3h, kk, ywb, full);
                    tma_2d(sb + G1_OFF_B3L + sp * TILEB, &tm_b3l, kk, ywb, full);
                }
            }
        }
        {
            int ls = (NC1 - 1) & 1;
            mbar_wait(sb + G1_MDONE(ls), mph[ls]);
        }
    }
    __syncthreads();
    fence_tc_after();

    if (wid < 4) {
        int m = wid * 32 + lane;
        bool valid = (m0 + m) < cnt;
        int row = rowbase + m;
        #pragma unroll
        for (int cb = 0; cb < 4; cb++) {
            uint32_t r1[32], r3[32];
            ldtm_x32(r1, tb + cb * 32);
            ldtm_x32(r3, tb + 128 + cb * 32);
            tmem_wait_ld();
            if (valid) {
                char* dh = (char*)(g_hmh + (size_t)row * F + n0 + cb * 32);
                char* dl = (char*)(g_hml + (size_t)row * F + n0 + cb * 32);
                #pragma unroll
                for (int c = 0; c < 32; c += 2) {
                    float g0 = __uint_as_float(r1[c]),     u0 = __uint_as_float(r3[c]);
                    float g1 = __uint_as_float(r1[c + 1]), u1 = __uint_as_float(r3[c + 1]);
                    float v0 = (g0 / (1.f + expf(-g0))) * u0;
                    float v1 = (g1 / (1.f + expf(-g1))) * u1;
                    uint16_t h0, l0, h1, l1;
                    bf16_split(v0, h0, l0);
                    bf16_split(v1, h1, l1);
                    *(uint32_t*)(dh + c * 2) = (uint32_t)h0 | ((uint32_t)h1 << 16);
                    *(uint32_t*)(dl + c * 2) = (uint32_t)l0 | ((uint32_t)l1 << 16);
                }
            }
        }
    }
    __syncthreads();
    if (wid == 0) tmem_dealloc(tb, 256);
#else
    // ---------- SIMT fallback ----------
    int e   = blockIdx.z;
    int cnt = g_count[e];
    int m0  = blockIdx.y * BM;
    if (m0 >= cnt) return;

    __shared__ float Xs[BM][33];
    __shared__ float B1s[32][64];
    __shared__ float B3s[32][64];
    __shared__ int   stok[BM];
    __shared__ int   sslot[BM];

    int tid = threadIdx.x;
    for (int i = tid; i < BM; i += 256) {
        int r = m0 + i;
        int slot = (r < cnt) ? g_list[e][r] : -1;
        sslot[i] = slot;
        stok[i]  = (slot >= 0) ? (slot >> 1) : -1;
    }
    __syncthreads();

    const float* w1p = W1 + (size_t)e * H * F;
    const float* w3p = W3 + (size_t)e * H * F;
    int tx = tid & 15, ty = tid >> 4;

    for (int half = 0; half < 2; half++) {
        int n0 = blockIdx.x * BN1 + half * 64;
        float acc1[8][4], acc3[8][4];
        #pragma unroll
        for (int i = 0; i < 8; i++)
            #pragma unroll
            for (int j = 0; j < 4; j++) { acc1[i][j] = 0.f; acc3[i][j] = 0.f; }

        for (int k0 = 0; k0 < H; k0 += 32) {
            __syncthreads();
            for (int i = tid; i < BM * 32; i += 256) {
                int m = i >> 5, k = i & 31;
                int tok = stok[m];
                Xs[m][k] = (tok >= 0) ? x[(size_t)tok * H + k0 + k] : 0.f;
            }
            for (int i = tid; i < 32 * 64; i += 256) {
                int k = i >> 6, n = i & 63;
                size_t off = (size_t)(k0 + k) * F + n0 + n;
                B1s[k][n] = w1p[off];
                B3s[k][n] = w3p[off];
            }
            __syncthreads();
            #pragma unroll
            for (int kk = 0; kk < 32; kk++) {
                float a[8], b1[4], b3[4];
                #pragma unroll
                for (int i = 0; i < 8; i++) a[i] = Xs[ty + 16 * i][kk];
                #pragma unroll
                for (int j = 0; j < 4; j++) { b1[j] = B1s[kk][tx + 16 * j]; b3[j] = B3s[kk][tx + 16 * j]; }
                #pragma unroll
                for (int i = 0; i < 8; i++)
                    #pragma unroll
                    for (int j = 0; j < 4; j++) {
                        acc1[i][j] += a[i] * b1[j];
                        acc3[i][j] += a[i] * b3[j];
                    }
            }
        }
        #pragma unroll
        for (int i = 0; i < 8; i++) {
            int m = ty + 16 * i;
            int slot = sslot[m];
            if (slot < 0) continue;
            float* dst = g_hmid + (size_t)slot * F + n0;
            #pragma unroll
            for (int j = 0; j < 4; j++) {
                float g = acc1[i][j];
                float u = acc3[i][j];
                float sg = g / (1.f + expf(-g));
                dst[tx + 16 * j] = sg * u;
            }
        }
        __syncthreads();
    }
#endif
}

// =============== GEMM2: hm @ W2^T * gate -> outpair ===============
#define G2_OFF_TMEM 0
#define G2_FULL(s)  (16 + 8*(s))
#define G2_MDONE(s) (48 + 8*(s))
#define G2_OFF_AH   1024
#define G2_OFF_AL   (G2_OFF_AH + 3*TILEB)
#define G2_OFF_BH   (G2_OFF_AL + 3*TILEB)
#define G2_OFF_BL   (G2_OFF_BH + 3*TILEB)
#define G2_SMEM     (G2_OFF_BL + 3*TILEB)

__global__ __launch_bounds__(256) void expert_down_mma(
    const float* __restrict__ W2,
    const __grid_constant__ CUtensorMap tm_ah,
    const __grid_constant__ CUtensorMap tm_al,
    const __grid_constant__ CUtensorMap tm_b2h,
    const __grid_constant__ CUtensorMap tm_b2l)
{
#if HAS_TCGEN05
    extern __shared__ char smem[];
    int e   = blockIdx.z;
    int cnt = g_count[e];
    int m0  = blockIdx.y * BM;
    if (m0 >= cnt) return;
    int n0  = blockIdx.x * BN2;
    int rowbase = g_off[e] + m0;

    uint32_t sb = smem_u32(smem);
    int tid = threadIdx.x, wid = tid >> 5, lane = tid & 31;
    if (tid == 0) {
        #pragma unroll
        for (int s = 0; s < 3; s++) { mbar_init(sb + G2_FULL(s), 1); mbar_init(sb + G2_MDONE(s), 1); }
    }
    if (wid == 0) tmem_alloc(sb + G2_OFF_TMEM, 128);
    __syncthreads();
    uint32_t tb;
    asm volatile("ld.shared.b32 %0, [%1];" : "=r"(tb) : "r"(sb + G2_OFF_TMEM));

    if (tid == 0) {
        int ywb = e * H + n0;
        #pragma unroll
        for (int p = 0; p < 3; p++) {
            uint32_t full = sb + G2_FULL(p);
            mbar_expect_tx(full, 4 * TILEB);
            int kk = p * BK;
            tma_2d(sb + G2_OFF_AH + p * TILEB, &tm_ah,  kk, rowbase, full);
            tma_2d(sb + G2_OFF_AL + p * TILEB, &tm_al,  kk, rowbase, full);
            tma_2d(sb + G2_OFF_BH + p * TILEB, &tm_b2h, kk, ywb, full);
            tma_2d(sb + G2_OFF_BL + p * TILEB, &tm_b2l, kk, ywb, full);
        }
        int fph[3] = {0, 0, 0}, mph[3] = {0, 0, 0};
        for (int kc = 0; kc < NC2; kc++) {
            int s = kc % 3;
            mbar_wait(sb + G2_FULL(s), fph[s]); fph[s] ^= 1;
            uint64_t adh = make_desc(sb + G2_OFF_AH + s * TILEB);
            uint64_t adl = make_desc(sb + G2_OFF_AL + s * TILEB);
            uint64_t bdh = make_desc(sb + G2_OFF_BH + s * TILEB);
            uint64_t bdl = make_desc(sb + G2_OFF_BL + s * TILEB);
            #pragma unroll
            for (int ks = 0; ks < 4; ks++) {
                uint32_t en0 = (kc == 0 && ks == 0) ? 0u : 1u;
                uint64_t o = ks * 2;
                mma_bf16_ss(tb, adh + o, bdh + o, IDESC_N(BN2), en0);
                mma_bf16_ss(tb, adl + o, bdh + o, IDESC_N(BN2), 1u);
                mma_bf16_ss(tb, adh + o, bdl + o, IDESC_N(BN2), 1u);
            }
            mma_commit(sb + G2_MDONE(s));
            // deferred refill: stage used at kc-1 gets chunk kc+2
            if (kc >= 1) {
                int pk = kc - 1, sp = pk % 3;
                mbar_wait(sb + G2_MDONE(sp), mph[sp]); mph[sp] ^= 1;
                if (pk + 3 < NC2) {
                    uint32_t full = sb + G2_FULL(sp);
                    mbar_expect_tx(full, 4 * TILEB);
                    int kk = (pk + 3) * BK;
                    tma_2d(sb + G2_OFF_AH + sp * TILEB, &tm_ah,  kk, rowbase, full);
                    tma_2d(sb + G2_OFF_AL + sp * TILEB, &tm_al,  kk, rowbase, full);
                    tma_2d(sb + G2_OFF_BH + sp * TILEB, &tm_b2h, kk, ywb, full);
                    tma_2d(sb + G2_OFF_BL + sp * TILEB, &tm_b2l, kk, ywb, full);
                }
            }
        }
        {
            int ls = (NC2 - 1) % 3;
            mbar_wait(sb + G2_MDONE(ls), mph[ls]);
        }
    }
    __syncthreads();
    fence_tc_after();

    if (wid < 4) {
        int m = wid * 32 + lane;
        bool valid = (m0 + m) < cnt;
        int row = rowbase + m;
        int slot = valid ? g_rowslot[row] : 0;
        float gw = valid ? g_wslot[slot] : 0.f;
        #pragma unroll
        for (int cb = 0; cb < 4; cb++) {
            uint32_t r0[32];
            ldtm_x32(r0, tb + cb * 32);
            tmem_wait_ld();
            if (valid) {
                float* dst = g_outpair + (size_t)slot * H + n0 + cb * 32;
                #pragma unroll
                for (int c = 0; c < 32; c += 4) {
                    float4 o;
                    #pragma unroll
                    for (int j = 0; j < 4; j++) (&o.x)[j] = gw * __uint_as_float(r0[c + j]);
                    *(float4*)(dst + c) = o;
                }
            }
        }
    }
    __syncthreads();
    if (wid == 0) tmem_dealloc(tb, 128);
#else
    // ---------- SIMT fallback ----------
    int e   = blockIdx.z;
    int cnt = g_count[e];
    int m0  = blockIdx.y * BM;
    if (m0 >= cnt) return;

    __shared__ float As[BM][33];
    __shared__ float Bs[32][64];
    __shared__ int   sslot[BM];

    int tid = threadIdx.x;
    for (int i = tid; i < BM; i += 256) {
        int r = m0 + i;
        sslot[i] = (r < cnt) ? g_list[e][r] : -1;
    }
    __syncthreads();

    const float* w2p = W2 + (size_t)e * F * H;
    int tx = tid & 15, ty = tid >> 4;

    for (int half = 0; half < 2; half++) {
        int n0 = blockIdx.x * BN2 + half * 64;
        float acc[8][4];
        #pragma unroll
        for (int i = 0; i < 8; i++)
            #pragma unroll
            for (int j = 0; j < 4; j++) acc[i][j] = 0.f;

        for (int k0 = 0; k0 < F; k0 += 32) {
            __syncthreads();
            for (int i = tid; i < BM * 32; i += 256) {
                int m = i >> 5, k = i & 31;
                int slot = sslot[m];
                As[m][k] = (slot >= 0) ? g_hmid[(size_t)slot * F + k0 + k] : 0.f;
            }
            for (int i = tid; i < 32 * 64; i += 256) {
                int k = i >> 6, n = i & 63;
                Bs[k][n] = w2p[(size_t)(k0 + k) * H + n0 + n];
            }
            __syncthreads();
            #pragma unroll
            for (int kk = 0; kk < 32; kk++) {
                float a[8], b[4];
                #pragma unroll
                for (int i = 0; i < 8; i++) a[i] = As[ty + 16 * i][kk];
                #pragma unroll
                for (int j = 0; j < 4; j++) b[j] = Bs[kk][tx + 16 * j];
                #pragma unroll
                for (int i = 0; i < 8; i++)
                    #pragma unroll
                    for (int j = 0; j < 4; j++) acc[i][j] += a[i] * b[j];
            }
        }
        #pragma unroll
        for (int i = 0; i < 8; i++) {
            int m = ty + 16 * i;
            int slot = sslot[m];
            if (slot < 0) continue;
            float gw = g_wslot[slot];
            float* dst = g_outpair + (size_t)slot * H + n0;
            #pragma unroll
            for (int j = 0; j < 4; j++) dst[tx + 16 * j] = gw * acc[i][j];
        }
        __syncthreads();
    }
#endif
}

__global__ __launch_bounds__(256) void combine_kernel(float* __restrict__ out)
{
    int i = blockIdx.x * 256 + threadIdx.x;
    if (i >= T * H) return;
    int t = i >> 10;
    int h = i & (H - 1);
    out[i] = g_outpair[(size_t)(2 * t) * H + h] + g_outpair[(size_t)(2 * t + 1) * H + h];
}

// =============== host ===============
typedef CUresult (*PFN_cuTensorMapEncodeTiled)(
    CUtensorMap*, CUtensorMapDataType, cuuint32_t, void*,
    const cuuint64_t*, const cuuint64_t*, const cuuint32_t*, const cuuint32_t*,
    CUtensorMapInterleave, CUtensorMapSwizzle, CUtensorMapL2promotion,
    CUtensorMapFloatOOBfill);

static PFN_cuTensorMapEncodeTiled get_encoder() {
    void* fn = nullptr;
    cudaDriverEntryPointQueryResult st;
    cudaGetDriverEntryPoint("cuTensorMapEncodeTiled", &fn, cudaEnableDefault, &st);
    return (PFN_cuTensorMapEncodeTiled)fn;
}

static void encode_2d(PFN_cuTensorMapEncodeTiled enc, CUtensorMap* tm, void* ptr,
                      uint64_t d0, uint64_t d1, uint32_t b0, uint32_t b1) {
    cuuint64_t dims[2] = {d0, d1};
    cuuint64_t strides[1] = {d0 * 2};   // bf16
    cuuint32_t box[2] = {b0, b1};
    cuuint32_t es[2] = {1, 1};
    enc(tm, CU_TENSOR_MAP_DATA_TYPE_BFLOAT16, 2, ptr, dims, strides, box, es,
        CU_TENSOR_MAP_INTERLEAVE_NONE, CU_TENSOR_MAP_SWIZZLE_128B,
        CU_TENSOR_MAP_L2_PROMOTION_L2_128B, CU_TENSOR_MAP_FLOAT_OOB_FILL_NONE);
}

extern "C" void kernel_launch(void* const* d_in, const int* in_sizes, int n_in,
                              void* d_out, int out_size)
{
    const float* x  = (const float*)d_in[0];
    const float* Wr = (const float*)d_in[1];
    const float* W1 = (const float*)d_in[2];
    const float* W2 = (const float*)d_in[3];
    const float* W3 = (const float*)d_in[4];
    float* out = (float*)d_out;

    __nv_bfloat16 *w1h, *w1l, *w3h, *w3l, *w2h, *w2l, *xgh, *xgl, *hmh, *hml;
    cudaGetSymbolAddress((void**)&w1h, g_w1h);
    cudaGetSymbolAddress((void**)&w1l, g_w1l);
    cudaGetSymbolAddress((void**)&w3h, g_w3h);
    cudaGetSymbolAddress((void**)&w3l, g_w3l);
    cudaGetSymbolAddress((void**)&w2h, g_w2h);
    cudaGetSymbolAddress((void**)&w2l, g_w2l);
    cudaGetSymbolAddress((void**)&xgh, g_xgh);
    cudaGetSymbolAddress((void**)&xgl, g_xgl);
    cudaGetSymbolAddress((void**)&hmh, g_hmh);
    cudaGetSymbolAddress((void**)&hml, g_hml);

    PFN_cuTensorMapEncodeTiled enc = get_encoder();
    CUtensorMap tm_xh, tm_xl, tm_b1h, tm_b1l, tm_b3h, tm_b3l;
    CUtensorMap tm_hh, tm_hl, tm_b2h, tm_b2l;
    if (enc) {
        encode_2d(enc, &tm_xh, xgh, H, SLOTS, BK, BM);
        encode_2d(enc, &tm_xl, xgl, H, SLOTS, BK, BM);
        encode_2d(enc, &tm_b1h, w1h, H, (uint64_t)E * F, BK, BN1);
        encode_2d(enc, &tm_b1l, w1l, H, (uint64_t)E * F, BK, BN1);
        encode_2d(enc, &tm_b3h, w3h, H, (uint64_t)E * F, BK, BN1);
        encode_2d(enc, &tm_b3l, w3l, H, (uint64_t)E * F, BK, BN1);
        encode_2d(enc, &tm_hh, hmh, F, SLOTS, BK, BM);
        encode_2d(enc, &tm_hl, hml, F, SLOTS, BK, BM);
        encode_2d(enc, &tm_b2h, w2h, F, (uint64_t)E * H, BK, BN2);
        encode_2d(enc, &tm_b2l, w2l, F, (uint64_t)E * H, BK, BN2);
    }

    cudaFuncSetAttribute(expert_up_mma,   cudaFuncAttributeMaxDynamicSharedMemorySize, G1_SMEM);
    cudaFuncSetAttribute(expert_down_mma, cudaFuncAttributeMaxDynamicSharedMemorySize, G2_SMEM);

    zero_counts_kernel<<<1, 32>>>();
    router_kernel<<<T, 256>>>(x, Wr);
    finalize_router_kernel<<<1, 1>>>();

    convert_x_kernel<<<(T * H) / (256 * 8), 256>>>(x);
    gather_x_kernel<<<SLOTS, 256>>>();
    {
        dim3 gw13(F / 32, H / 32, E);
        transpose_split_kernel<<<gw13, 256>>>(W1, w1h, w1l, H, F);
        transpose_split_kernel<<<gw13, 256>>>(W3, w3h, w3l, H, F);
        dim3 gw2(H / 32, F / 32, E);
        transpose_split_kernel<<<gw2, 256>>>(W2, w2h, w2l, F, H);
    }

    dim3 g1(F / BN1, MT_MAX, E);
    expert_up_mma<<<g1, 256, G1_SMEM>>>(x, W1, W3, tm_xh, tm_xl,
                                        tm_b1h, tm_b1l, tm_b3h, tm_b3l);

    dim3 g2(H / BN2, MT_MAX, E);
    expert_down_mma<<<g2, 256, G2_SMEM>>>(W2, tm_hh, tm_hl, tm_b2h, tm_b2l);

    combine_kernel<<<(T * H + 255) / 256, 256>>>(out);
}

// round 12
// speedup vs baseline: 6.8452x; 1.0192x over previous
#include <cuda_runtime.h>
#include <cuda.h>
#include <cuda_bf16.h>
#include <cstdint>
#include <math.h>

#define H 1024
#define F 4096
#define E 8
#define T 2048
#define SLOTS (2*T)

#define BM1 256        // GEMM1 m-tile (two M=128 halves)
#define BN1 128
#define BN2 256        // GEMM2 n-tile (two N=128 halves)
#define BK 64
#define NC1 (H/BK)     // 16
#define NC2 (F/BK)     // 64
#define MT1 (T/BM1)    // 8
#define MT2 (T/128)    // 16

#if defined(__CUDA_ARCH_FEAT_SM103_ALL) || defined(__CUDA_ARCH_FEAT_SM100_ALL) || \
    (defined(__CUDA_ARCH_SPECIFIC__) && (__CUDA_ARCH_SPECIFIC__ == 1030)) || \
    (defined(__CUDA_ARCH_FAMILY_SPECIFIC__) && (__CUDA_ARCH_FAMILY_SPECIFIC__ == 1030))
#define HAS_TCGEN05 1
#else
#define HAS_TCGEN05 0
#endif

__device__ int   g_count[E];
__device__ int   g_off[E + 1];
__device__ int   g_list[E][T];
__device__ int   g_rowslot[SLOTS];
__device__ __align__(1024) float g_wslot[SLOTS];
__device__ __align__(1024) float g_hmid[(size_t)SLOTS * F];      // SIMT fallback only
__device__ __align__(1024) float g_outpair[(size_t)SLOTS * H];

__device__ __align__(1024) __nv_bfloat16 g_xh[(size_t)T * H];
__device__ __align__(1024) __nv_bfloat16 g_xl[(size_t)T * H];
__device__ __align__(1024) __nv_bfloat16 g_xgh[(size_t)SLOTS * H];
__device__ __align__(1024) __nv_bfloat16 g_xgl[(size_t)SLOTS * H];
__device__ __align__(1024) __nv_bfloat16 g_w1h[(size_t)E*F*H];
__device__ __align__(1024) __nv_bfloat16 g_w1l[(size_t)E*F*H];
__device__ __align__(1024) __nv_bfloat16 g_w3h[(size_t)E*F*H];
__device__ __align__(1024) __nv_bfloat16 g_w3l[(size_t)E*F*H];
__device__ __align__(1024) __nv_bfloat16 g_w2h[(size_t)E*H*F];
__device__ __align__(1024) __nv_bfloat16 g_w2l[(size_t)E*H*F];
__device__ __align__(1024) __nv_bfloat16 g_hmh[(size_t)SLOTS*F];
__device__ __align__(1024) __nv_bfloat16 g_hml[(size_t)SLOTS*F];

__device__ __forceinline__ uint32_t smem_u32(const void* p) {
    uint32_t a;
    asm("{ .reg .u64 t; cvta.to.shared.u64 t, %1; cvt.u32.u64 %0, t; }" : "=r"(a) : "l"(p));
    return a;
}

__device__ __forceinline__ void bf16_split(float v, uint16_t& hi, uint16_t& lo) {
    __nv_bfloat16 h = __float2bfloat16(v);
    __nv_bfloat16 l = __float2bfloat16(v - __bfloat162float(h));
    hi = __bfloat16_as_ushort(h);
    lo = __bfloat16_as_ushort(l);
}

#if HAS_TCGEN05
static __device__ __forceinline__ uint64_t make_desc(uint32_t addr) {
    const uint64_t base = (uint64_t(2) << 61) | (uint64_t(1) << 46) |
                          (uint64_t(64) << 32) | (uint64_t(1) << 16);
    return base | ((uint64_t)(addr >> 4) & 0x3FFF);
}

#define IDESC_128 ((1u << 4) | (1u << 7) | (1u << 10) | ((128 / 8) << 17) | ((128 / 16) << 24))

__device__ __forceinline__ void mma_bf16_ss(uint32_t d, uint64_t ad, uint64_t bd, uint32_t en) {
    asm volatile(
        "{\n\t.reg .pred p;\n\t"
        "setp.ne.u32 p, %4, 0;\n\t"
        "tcgen05.mma.cta_group::1.kind::f16 [%0], %1, %2, %3, {%5,%5,%5,%5}, p;\n\t}"
        :: "r"(d), "l"(ad), "l"(bd), "r"(IDESC_128), "r"(en), "r"(0u) : "memory");
}
__device__ __forceinline__ void tmem_alloc(uint32_t smem_dst, uint32_t ncols) {
    asm volatile("tcgen05.alloc.cta_group::1.sync.aligned.shared::cta.b32 [%0], %1;"
                 :: "r"(smem_dst), "r"(ncols) : "memory");
}
__device__ __forceinline__ void tmem_dealloc(uint32_t tb, uint32_t ncols) {
    asm volatile("tcgen05.relinquish_alloc_permit.cta_group::1.sync.aligned;");
    asm volatile("tcgen05.dealloc.cta_group::1.sync.aligned.b32 %0, %1;" :: "r"(tb), "r"(ncols));
}
__device__ __forceinline__ void mma_commit(uint32_t mbar) {
    asm volatile("tcgen05.commit.cta_group::1.mbarrier::arrive::one.shared::cluster.b64 [%0];"
                 :: "r"(mbar) : "memory");
}
__device__ __forceinline__ void mbar_init(uint32_t mbar, uint32_t cnt) {
    asm volatile("mbarrier.init.shared.b64 [%0], %1;" :: "r"(mbar), "r"(cnt) : "memory");
}
__device__ __forceinline__ void mbar_wait(uint32_t mbar, uint32_t parity) {
    uint32_t done;
    asm volatile(
        "{\n\t.reg .pred p;\n\t"
        "mbarrier.try_wait.parity.acquire.cta.shared::cta.b64 p, [%1], %2;\n\t"
        "selp.b32 %0, 1, 0, p;\n\t}"
        : "=r"(done) : "r"(mbar), "r"(parity) : "memory");
    if (!done) {
        asm volatile(
            "{\n\t.reg .pred P1;\n\t"
            "W_%=:\n\t"
            "mbarrier.try_wait.parity.acquire.cta.shared::cta.b64 P1, [%0], %1, 0x989680;\n\t"
            "@P1 bra.uni D_%=;\n\t"
            "bra.uni W_%=;\n\t"
            "D_%=:\n\t}"
            :: "r"(mbar), "r"(parity) : "memory");
    }
}
__device__ __forceinline__ void mbar_expect_tx(uint32_t mbar, uint32_t bytes) {
    asm volatile("mbarrier.arrive.expect_tx.shared.b64 _, [%0], %1;"
                 :: "r"(mbar), "r"(bytes) : "memory");
}
__device__ __forceinline__ void tma_2d(uint32_t dst, const CUtensorMap* map,
                                       int x, int y, uint32_t mbar) {
    asm volatile(
        "cp.async.bulk.tensor.2d.shared::cta.global.tile.mbarrier::complete_tx::bytes "
        "[%0], [%1, {%2, %3}], [%4];"
        :: "r"(dst), "l"(map), "r"(x), "r"(y), "r"(mbar) : "memory");
}
__device__ __forceinline__ void fence_tc_after() {
    asm volatile("tcgen05.fence::after_thread_sync;" ::: "memory");
}
__device__ __forceinline__ void ldtm_x32(uint32_t* r, uint32_t a) {
    asm volatile(
        "tcgen05.ld.sync.aligned.32x32b.x32.b32 "
        "{%0,%1,%2,%3,%4,%5,%6,%7,%8,%9,%10,%11,%12,%13,%14,%15,"
        "%16,%17,%18,%19,%20,%21,%22,%23,%24,%25,%26,%27,%28,%29,%30,%31}, [%32];"
        : "=r"(r[0]), "=r"(r[1]), "=r"(r[2]), "=r"(r[3]), "=r"(r[4]), "=r"(r[5]),
          "=r"(r[6]), "=r"(r[7]), "=r"(r[8]), "=r"(r[9]), "=r"(r[10]), "=r"(r[11]),
          "=r"(r[12]), "=r"(r[13]), "=r"(r[14]), "=r"(r[15]), "=r"(r[16]), "=r"(r[17]),
          "=r"(r[18]), "=r"(r[19]), "=r"(r[20]), "=r"(r[21]), "=r"(r[22]), "=r"(r[23]),
          "=r"(r[24]), "=r"(r[25]), "=r"(r[26]), "=r"(r[27]), "=r"(r[28]), "=r"(r[29]),
          "=r"(r[30]), "=r"(r[31])
        : "r"(a));
}
__device__ __forceinline__ void tmem_wait_ld() {
    asm volatile("tcgen05.wait::ld.sync.aligned;" ::: "memory");
}
#endif // HAS_TCGEN05

// =============== prep kernels ===============
__global__ void zero_counts_kernel() {
    if (threadIdx.x < E) g_count[threadIdx.x] = 0;
}

__global__ __launch_bounds__(256) void router_kernel(
    const float* __restrict__ x, const float* __restrict__ Wr)
{
    int t = blockIdx.x;
    __shared__ float xs[H];
    __shared__ float logits[E];
    int tid = threadIdx.x;
    for (int i = tid; i < H; i += 256) xs[i] = x[(size_t)t * H + i];
    __syncthreads();
    int w = tid >> 5, lane = tid & 31;
    {
        const float* wr = Wr + w * H;
        float s = 0.f;
        for (int i = lane; i < H; i += 32) s += xs[i] * wr[i];
        #pragma unroll
        for (int off = 16; off; off >>= 1) s += __shfl_xor_sync(0xffffffffu, s, off);
        if (lane == 0) logits[w] = s;
    }
    __syncthreads();
    if (tid == 0) {
        int e0 = 0; float b0 = logits[0];
        #pragma unroll
        for (int e = 1; e < E; e++) if (logits[e] > b0) { b0 = logits[e]; e0 = e; }
        int e1 = -1; float b1 = -3.0e38f;
        #pragma unroll
        for (int e = 0; e < E; e++) if (e != e0 && logits[e] > b1) { b1 = logits[e]; e1 = e; }
        float w0 = 1.f / (1.f + expf(b1 - b0));
        float w1 = 1.f - w0;
        int p0 = atomicAdd(&g_count[e0], 1);
        int p1 = atomicAdd(&g_count[e1], 1);
        g_list[e0][p0] = 2 * t;
        g_list[e1][p1] = 2 * t + 1;
        g_wslot[2 * t]     = w0;
        g_wslot[2 * t + 1] = w1;
    }
}

__global__ void finalize_router_kernel() {
    int o = 0;
    #pragma unroll
    for (int e = 0; e < E; e++) { g_off[e] = o; o += g_count[e]; }
    g_off[E] = o;
}

__global__ __launch_bounds__(256) void convert_x_kernel(const float* __restrict__ x)
{
    size_t i = ((size_t)blockIdx.x * 256 + threadIdx.x) * 8;
    float v[8];
    *(float4*)(v)     = *(const float4*)(x + i);
    *(float4*)(v + 4) = *(const float4*)(x + i + 4);
    uint16_t h[8], l[8];
    #pragma unroll
    for (int j = 0; j < 8; j++) bf16_split(v[j], h[j], l[j]);
    uint4 ph = make_uint4((uint32_t)h[0] | ((uint32_t)h[1] << 16),
                          (uint32_t)h[2] | ((uint32_t)h[3] << 16),
                          (uint32_t)h[4] | ((uint32_t)h[5] << 16),
                          (uint32_t)h[6] | ((uint32_t)h[7] << 16));
    uint4 pl = make_uint4((uint32_t)l[0] | ((uint32_t)l[1] << 16),
                          (uint32_t)l[2] | ((uint32_t)l[3] << 16),
                          (uint32_t)l[4] | ((uint32_t)l[5] << 16),
                          (uint32_t)l[6] | ((uint32_t)l[7] << 16));
    *(uint4*)((char*)g_xh + i * 2) = ph;
    *(uint4*)((char*)g_xl + i * 2) = pl;
}

__global__ __launch_bounds__(256) void gather_x_kernel()
{
    int r = blockIdx.x;
    int e = 0;
    while (e < E - 1 && r >= g_off[e + 1]) e++;
    int p = r - g_off[e];
    int slot = g_list[e][p];
    if (threadIdx.x == 0) g_rowslot[r] = slot;
    size_t so = (size_t)(slot >> 1) * H;
    size_t dof = (size_t)r * H;
    ((uint2*)(g_xgh + dof))[threadIdx.x] = ((const uint2*)(g_xh + so))[threadIdx.x];
    ((uint2*)(g_xgl + dof))[threadIdx.x] = ((const uint2*)(g_xl + so))[threadIdx.x];
}

// transpose + split: src [E][K][N] fp32 -> dh/dl [E][N][K] bf16 (fixed: 4 elem/thread)
__global__ __launch_bounds__(256) void transpose_split_kernel(
    const float* __restrict__ src,
    __nv_bfloat16* __restrict__ dh,
    __nv_bfloat16* __restrict__ dl,
    int K, int N)
{
    __shared__ float ts[32][33];
    int e = blockIdx.z;
    size_t base = (size_t)e * K * N;
    int n0 = blockIdx.x * 32, k0 = blockIdx.y * 32;
    int tx = threadIdx.x & 31, ty = threadIdx.x >> 5;
    #pragma unroll
    for (int r = 0; r < 4; r++) {
        int k = k0 + ty + 8 * r;
        ts[ty + 8 * r][tx] = src[base + (size_t)k * N + n0 + tx];
    }
    __syncthreads();
    int nl = threadIdx.x >> 3;
    int kg = threadIdx.x & 7;
    uint16_t hv[4], lv[4];
    #pragma unroll
    for (int j = 0; j < 4; j++) {
        float v = ts[kg * 4 + j][nl];
        bf16_split(v, hv[j], lv[j]);
    }
    uint2 ph = make_uint2((uint32_t)hv[0] | ((uint32_t)hv[1] << 16),
                          (uint32_t)hv[2] | ((uint32_t)hv[3] << 16));
    uint2 pl = make_uint2((uint32_t)lv[0] | ((uint32_t)lv[1] << 16),
                          (uint32_t)lv[2] | ((uint32_t)lv[3] << 16));
    size_t o = base + (size_t)(n0 + nl) * K + k0 + kg * 4;
    *(uint2*)(dh + o) = ph;
    *(uint2*)(dl + o) = pl;
}

// =============== GEMM1: Xg[256-rows] @ (W1,W3)^T -> silu*up -> hm ===============
// A (two 128-row halves) single-buffered (32KB/plane); B double-buffered.
#define TILEB 16384
#define G1_OFF_TMEM 0
#define G1_BFULL(s) (16 + 8*(s))
#define G1_MDONE(s) (32 + 8*(s))
#define G1_AFULL    48
#define G1_OFF_AH   1024
#define G1_OFF_AL   (G1_OFF_AH  + 32768)
#define G1_OFF_B1H  (G1_OFF_AL  + 32768)
#define G1_OFF_B1L  (G1_OFF_B1H + 2*TILEB)
#define G1_OFF_B3H  (G1_OFF_B1L + 2*TILEB)
#define G1_OFF_B3L  (G1_OFF_B3H + 2*TILEB)
#define G1_SMEM     (G1_OFF_B3L + 2*TILEB)

__global__ __launch_bounds__(256) void expert_up_mma(
    const float* __restrict__ x,
    const float* __restrict__ W1,
    const float* __restrict__ W3,
    const __grid_constant__ CUtensorMap tm_ah,
    const __grid_constant__ CUtensorMap tm_al,
    const __grid_constant__ CUtensorMap tm_b1h,
    const __grid_constant__ CUtensorMap tm_b1l,
    const __grid_constant__ CUtensorMap tm_b3h,
    const __grid_constant__ CUtensorMap tm_b3l)
{
#if HAS_TCGEN05
    extern __shared__ char smem[];
    int e   = blockIdx.z;
    int cnt = g_count[e];
    int m0  = blockIdx.y * BM1;
    if (m0 >= cnt) return;
    int n0  = blockIdx.x * BN1;
    int rowbase = g_off[e] + m0;

    uint32_t sb = smem_u32(smem);
    int tid = threadIdx.x, wid = tid >> 5, lane = tid & 31;
    if (tid == 0) {
        #pragma unroll
        for (int s = 0; s < 2; s++) { mbar_init(sb + G1_BFULL(s), 1); mbar_init(sb + G1_MDONE(s), 1); }
        mbar_init(sb + G1_AFULL, 1);
    }
    if (wid == 0) tmem_alloc(sb + G1_OFF_TMEM, 512);
    __syncthreads();
    uint32_t tb;
    asm volatile("ld.shared.b32 %0, [%1];" : "=r"(tb) : "r"(sb + G1_OFF_TMEM));

    if (tid == 0) {
        int ywb = e * F + n0;
        // prologue: A chunk 0; B chunks 0,1
        mbar_expect_tx(sb + G1_AFULL, 65536);
        tma_2d(sb + G1_OFF_AH, &tm_ah, 0, rowbase, sb + G1_AFULL);
        tma_2d(sb + G1_OFF_AL, &tm_al, 0, rowbase, sb + G1_AFULL);
        #pragma unroll
        for (int p = 0; p < 2; p++) {
            uint32_t full = sb + G1_BFULL(p);
            mbar_expect_tx(full, 4 * TILEB);
            int kk = p * BK;
            tma_2d(sb + G1_OFF_B1H + p * TILEB, &tm_b1h, kk, ywb, full);
            tma_2d(sb + G1_OFF_B1L + p * TILEB, &tm_b1l, kk, ywb, full);
            tma_2d(sb + G1_OFF_B3H + p * TILEB, &tm_b3h, kk, ywb, full);
            tma_2d(sb + G1_OFF_B3L + p * TILEB, &tm_b3l, kk, ywb, full);
        }
        int bph[2] = {0, 0}, mph[2] = {0, 0}, aph = 0;
        for (int kc = 0; kc < NC1; kc++) {
            int s = kc & 1;
            if (kc >= 1) {
                int sp = (kc - 1) & 1;
                mbar_wait(sb + G1_MDONE(sp), mph[sp]); mph[sp] ^= 1;  // chunk kc-1 done
                // A buffer free -> load chunk kc
                mbar_expect_tx(sb + G1_AFULL, 65536);
                tma_2d(sb + G1_OFF_AH, &tm_ah, kc * BK, rowbase, sb + G1_AFULL);
                tma_2d(sb + G1_OFF_AL, &tm_al, kc * BK, rowbase, sb + G1_AFULL);
                // B stage sp free -> load chunk kc+1
                if (kc + 1 < NC1) {
                    uint32_t full = sb + G1_BFULL(sp);
                    mbar_expect_tx(full, 4 * TILEB);
                    int kk = (kc + 1) * BK;
                    tma_2d(sb + G1_OFF_B1H + sp * TILEB, &tm_b1h, kk, ywb, full);
                    tma_2d(sb + G1_OFF_B1L + sp * TILEB, &tm_b1l, kk, ywb, full);
                    tma_2d(sb + G1_OFF_B3H + sp * TILEB, &tm_b3h, kk, ywb, full);
                    tma_2d(sb + G1_OFF_B3L + sp * TILEB, &tm_b3l, kk, ywb, full);
                }
            }
            mbar_wait(sb + G1_BFULL(s), bph[s]); bph[s] ^= 1;
            mbar_wait(sb + G1_AFULL, aph); aph ^= 1;
            uint64_t adh = make_desc(sb + G1_OFF_AH);
            uint64_t adl = make_desc(sb + G1_OFF_AL);
            uint64_t b1h = make_desc(sb + G1_OFF_B1H + s * TILEB);
            uint64_t b1l = make_desc(sb + G1_OFF_B1L + s * TILEB);
            uint64_t b3h = make_desc(sb + G1_OFF_B3H + s * TILEB);
            uint64_t b3l = make_desc(sb + G1_OFF_B3L + s * TILEB);
            #pragma unroll
            for (int ks = 0; ks < 4; ks++) {
                uint32_t en0 = (kc == 0 && ks == 0) ? 0u : 1u;
                uint64_t bo = ks * 2;
                #pragma unroll
                for (int h = 0; h < 2; h++) {
                    uint64_t ao = h * 1024 + ks * 2;     // +128 rows = 16KB = 1024 units
                    uint32_t d1 = tb + h * 256;          // acc1
                    uint32_t d3 = tb + h * 256 + 128;    // acc3
                    mma_bf16_ss(d1, adh + ao, b1h + bo, en0);
                    mma_bf16_ss(d1, adl + ao, b1h + bo, 1u);
                    mma_bf16_ss(d1, adh + ao, b1l + bo, 1u);
                    mma_bf16_ss(d3, adh + ao, b3h + bo, en0);
                    mma_bf16_ss(d3, adl + ao, b3h + bo, 1u);
                    mma_bf16_ss(d3, adh + ao, b3l + bo, 1u);
                }
            }
            mma_commit(sb + G1_MDONE(s));
        }
        {
            int ls = (NC1 - 1) & 1;
            mbar_wait(sb + G1_MDONE(ls), mph[ls]);
        }
    }
    __syncthreads();
    fence_tc_after();

    if (wid < 4) {
        int m = wid * 32 + lane;
        #pragma unroll
        for (int h = 0; h < 2; h++) {
            bool valid = (m0 + h * 128 + m) < cnt;
            int row = rowbase + h * 128 + m;
            #pragma unroll
            for (int cb = 0; cb < 4; cb++) {
                uint32_t r1[32], r3[32];
                ldtm_x32(r1, tb + h * 256 + cb * 32);
                ldtm_x32(r3, tb + h * 256 + 128 + cb * 32);
                tmem_wait_ld();
                if (valid) {
                    char* dh = (char*)(g_hmh + (size_t)row * F + n0 + cb * 32);
                    char* dl = (char*)(g_hml + (size_t)row * F + n0 + cb * 32);
                    #pragma unroll
                    for (int c = 0; c < 32; c += 2) {
                        float g0 = __uint_as_float(r1[c]),     u0 = __uint_as_float(r3[c]);
                        float g1 = __uint_as_float(r1[c + 1]), u1 = __uint_as_float(r3[c + 1]);
                        float v0 = (g0 / (1.f + expf(-g0))) * u0;
                        float v1 = (g1 / (1.f + expf(-g1))) * u1;
                        uint16_t h0, l0, h1, l1;
                        bf16_split(v0, h0, l0);
                        bf16_split(v1, h1, l1);
                        *(uint32_t*)(dh + c * 2) = (uint32_t)h0 | ((uint32_t)h1 << 16);
                        *(uint32_t*)(dl + c * 2) = (uint32_t)l0 | ((uint32_t)l1 << 16);
                    }
                }
            }
        }
    }
    __syncthreads();
    if (wid == 0) tmem_dealloc(tb, 512);
#else
    // ---------- SIMT fallback (two 128-row subtiles, two 64-col halves) ----------
    int e   = blockIdx.z;
    int cnt = g_count[e];
    int m0b = blockIdx.y * BM1;
    if (m0b >= cnt) return;

    __shared__ float Xs[128][33];
    __shared__ float B1s[32][64];
    __shared__ float B3s[32][64];
    __shared__ int   stok[128];
    __shared__ int   sslot[128];

    int tid = threadIdx.x;
    const float* w1p = W1 + (size_t)e * H * F;
    const float* w3p = W3 + (size_t)e * H * F;
    int tx = tid & 15, ty = tid >> 4;

    for (int sub = 0; sub < 2; sub++) {
        int m0 = m0b + sub * 128;
        if (m0 >= cnt) break;
        __syncthreads();
        for (int i = tid; i < 128; i += 256) {
            int r = m0 + i;
            int slot = (r < cnt) ? g_list[e][r] : -1;
            sslot[i] = slot;
            stok[i]  = (slot >= 0) ? (slot >> 1) : -1;
        }
        __syncthreads();
        for (int half = 0; half < 2; half++) {
            int n0 = blockIdx.x * BN1 + half * 64;
            float acc1[8][4], acc3[8][4];
            #pragma unroll
            for (int i = 0; i < 8; i++)
                #pragma unroll
                for (int j = 0; j < 4; j++) { acc1[i][j] = 0.f; acc3[i][j] = 0.f; }
            for (int k0 = 0; k0 < H; k0 += 32) {
                __syncthreads();
                for (int i = tid; i < 128 * 32; i += 256) {
                    int m = i >> 5, k = i & 31;
                    int tok = stok[m];
                    Xs[m][k] = (tok >= 0) ? x[(size_t)tok * H + k0 + k] : 0.f;
                }
                for (int i = tid; i < 32 * 64; i += 256) {
                    int k = i >> 6, n = i & 63;
                    size_t off = (size_t)(k0 + k) * F + n0 + n;
                    B1s[k][n] = w1p[off];
                    B3s[k][n] = w3p[off];
                }
                __syncthreads();
                #pragma unroll
                for (int kk = 0; kk < 32; kk++) {
                    float a[8], b1[4], b3[4];
                    #pragma unroll
                    for (int i = 0; i < 8; i++) a[i] = Xs[ty + 16 * i][kk];
                    #pragma unroll
                    for (int j = 0; j < 4; j++) { b1[j] = B1s[kk][tx + 16 * j]; b3[j] = B3s[kk][tx + 16 * j]; }
                    #pragma unroll
                    for (int i = 0; i < 8; i++)
                        #pragma unroll
                        for (int j = 0; j < 4; j++) {
                            acc1[i][j] += a[i] * b1[j];
                            acc3[i][j] += a[i] * b3[j];
                        }
                }
            }
            #pragma unroll
            for (int i = 0; i < 8; i++) {
                int m = ty + 16 * i;
                int slot = sslot[m];
                if (slot < 0) continue;
                float* dst = g_hmid + (size_t)slot * F + n0;
                #pragma unroll
                for (int j = 0; j < 4; j++) {
                    float g = acc1[i][j];
                    float u = acc3[i][j];
                    float sg = g / (1.f + expf(-g));
                    dst[tx + 16 * j] = sg * u;
                }
            }
            __syncthreads();
        }
    }
#endif
}

// =============== GEMM2: hm @ W2^T (256 n-cols) * gate -> outpair ===============
#define G2_OFF_TMEM 0
#define G2_FULL(s)  (16 + 8*(s))
#define G2_MDONE(s) (32 + 8*(s))
#define G2_OFF_AH   1024
#define G2_OFF_AL   (G2_OFF_AH + 2*TILEB)
#define G2_OFF_BH   (G2_OFF_AL + 2*TILEB)
#define G2_OFF_BL   (G2_OFF_BH + 2*32768)
#define G2_SMEM     (G2_OFF_BL + 2*32768)

__global__ __launch_bounds__(256) void expert_down_mma(
    const float* __restrict__ W2,
    const __grid_constant__ CUtensorMap tm_ah,
    const __grid_constant__ CUtensorMap tm_al,
    const __grid_constant__ CUtensorMap tm_b2h,
    const __grid_constant__ CUtensorMap tm_b2l)
{
#if HAS_TCGEN05
    extern __shared__ char smem[];
    int e   = blockIdx.z;
    int cnt = g_count[e];
    int m0  = blockIdx.y * 128;
    if (m0 >= cnt) return;
    int n0  = blockIdx.x * BN2;
    int rowbase = g_off[e] + m0;

    uint32_t sb = smem_u32(smem);
    int tid = threadIdx.x, wid = tid >> 5, lane = tid & 31;
    if (tid == 0) {
        #pragma unroll
        for (int s = 0; s < 2; s++) { mbar_init(sb + G2_FULL(s), 1); mbar_init(sb + G2_MDONE(s), 1); }
    }
    if (wid == 0) tmem_alloc(sb + G2_OFF_TMEM, 256);
    __syncthreads();
    uint32_t tb;
    asm volatile("ld.shared.b32 %0, [%1];" : "=r"(tb) : "r"(sb + G2_OFF_TMEM));

    if (tid == 0) {
        int ywb = e * H + n0;
        #pragma unroll
        for (int p = 0; p < 2; p++) {
            uint32_t full = sb + G2_FULL(p);
            mbar_expect_tx(full, 2 * TILEB + 2 * 32768);
            int kk = p * BK;
            tma_2d(sb + G2_OFF_AH + p * TILEB,  &tm_ah,  kk, rowbase, full);
            tma_2d(sb + G2_OFF_AL + p * TILEB,  &tm_al,  kk, rowbase, full);
            tma_2d(sb + G2_OFF_BH + p * 32768, &tm_b2h, kk, ywb, full);
            tma_2d(sb + G2_OFF_BL + p * 32768, &tm_b2l, kk, ywb, full);
        }
        int fph[2] = {0, 0}, mph[2] = {0, 0};
        for (int kc = 0; kc < NC2; kc++) {
            int s = kc & 1;
            mbar_wait(sb + G2_FULL(s), fph[s]); fph[s] ^= 1;
            uint64_t adh = make_desc(sb + G2_OFF_AH + s * TILEB);
            uint64_t adl = make_desc(sb + G2_OFF_AL + s * TILEB);
            uint64_t bdh = make_desc(sb + G2_OFF_BH + s * 32768);
            uint64_t bdl = make_desc(sb + G2_OFF_BL + s * 32768);
            #pragma unroll
            for (int ks = 0; ks < 4; ks++) {
                uint32_t en0 = (kc == 0 && ks == 0) ? 0u : 1u;
                uint64_t ao = ks * 2;
                #pragma unroll
                for (int nh = 0; nh < 2; nh++) {
                    uint64_t bo = nh * 1024 + ks * 2;   // +128 B-rows = 16KB = 1024 units
                    uint32_t d = tb + nh * 128;
                    mma_bf16_ss(d, adh + ao, bdh + bo, en0);
                    mma_bf16_ss(d, adl + ao, bdh + bo, 1u);
                    mma_bf16_ss(d, adh + ao, bdl + bo, 1u);
                }
            }
            mma_commit(sb + G2_MDONE(s));
            // deferred refill: stage used at kc-1 gets chunk kc+1
            if (kc >= 1) {
                int sp = (kc - 1) & 1;
                mbar_wait(sb + G2_MDONE(sp), mph[sp]); mph[sp] ^= 1;
                if (kc + 1 < NC2) {
                    uint32_t full = sb + G2_FULL(sp);
                    mbar_expect_tx(full, 2 * TILEB + 2 * 32768);
                    int kk = (kc + 1) * BK;
                    tma_2d(sb + G2_OFF_AH + sp * TILEB,  &tm_ah,  kk, rowbase, full);
                    tma_2d(sb + G2_OFF_AL + sp * TILEB,  &tm_al,  kk, rowbase, full);
                    tma_2d(sb + G2_OFF_BH + sp * 32768, &tm_b2h, kk, ywb, full);
                    tma_2d(sb + G2_OFF_BL + sp * 32768, &tm_b2l, kk, ywb, full);
                }
            }
        }
        {
            int ls = (NC2 - 1) & 1;
            mbar_wait(sb + G2_MDONE(ls), mph[ls]);
        }
    }
    __syncthreads();
    fence_tc_after();

    if (wid < 4) {
        int m = wid * 32 + lane;
        bool valid = (m0 + m) < cnt;
        int row = rowbase + m;
        int slot = valid ? g_rowslot[row] : 0;
        float gw = valid ? g_wslot[slot] : 0.f;
        #pragma unroll
        for (int cb = 0; cb < 8; cb++) {
            uint32_t r0[32];
            ldtm_x32(r0, tb + cb * 32);
            tmem_wait_ld();
            if (valid) {
                float* dst = g_outpair + (size_t)slot * H + n0 + cb * 32;
                #pragma unroll
                for (int c = 0; c < 32; c += 4) {
                    float4 o;
                    #pragma unroll
                    for (int j = 0; j < 4; j++) (&o.x)[j] = gw * __uint_as_float(r0[c + j]);
                    *(float4*)(dst + c) = o;
                }
            }
        }
    }
    __syncthreads();
    if (wid == 0) tmem_dealloc(tb, 256);
#else
    // ---------- SIMT fallback (four 64-col quarters of the 256 tile) ----------
    int e   = blockIdx.z;
    int cnt = g_count[e];
    int m0  = blockIdx.y * 128;
    if (m0 >= cnt) return;

    __shared__ float As[128][33];
    __shared__ float Bs[32][64];
    __shared__ int   sslot[128];

    int tid = threadIdx.x;
    for (int i = tid; i < 128; i += 256) {
        int r = m0 + i;
        sslot[i] = (r < cnt) ? g_list[e][r] : -1;
    }
    __syncthreads();

    const float* w2p = W2 + (size_t)e * F * H;
    int tx = tid & 15, ty = tid >> 4;

    for (int half = 0; half < 4; half++) {
        int n0 = blockIdx.x * BN2 + half * 64;
        float acc[8][4];
        #pragma unroll
        for (int i = 0; i < 8; i++)
            #pragma unroll
            for (int j = 0; j < 4; j++) acc[i][j] = 0.f;

        for (int k0 = 0; k0 < F; k0 += 32) {
            __syncthreads();
            for (int i = tid; i < 128 * 32; i += 256) {
                int m = i >> 5, k = i & 31;
                int slot = sslot[m];
                As[m][k] = (slot >= 0) ? g_hmid[(size_t)slot * F + k0 + k] : 0.f;
            }
            for (int i = tid; i < 32 * 64; i += 256) {
                int k = i >> 6, n = i & 63;
                Bs[k][n] = w2p[(size_t)(k0 + k) * H + n0 + n];
            }
            __syncthreads();
            #pragma unroll
            for (int kk = 0; kk < 32; kk++) {
                float a[8], b[4];
                #pragma unroll
                for (int i = 0; i < 8; i++) a[i] = As[ty + 16 * i][kk];
                #pragma unroll
                for (int j = 0; j < 4; j++) b[j] = Bs[kk][tx + 16 * j];
                #pragma unroll
                for (int i = 0; i < 8; i++)
                    #pragma unroll
                    for (int j = 0; j < 4; j++) acc[i][j] += a[i] * b[j];
            }
        }
        #pragma unroll
        for (int i = 0; i < 8; i++) {
            int m = ty + 16 * i;
            int slot = sslot[m];
            if (slot < 0) continue;
            float gw = g_wslot[slot];
            float* dst = g_outpair + (size_t)slot * H + n0;
            #pragma unroll
            for (int j = 0; j < 4; j++) dst[tx + 16 * j] = gw * acc[i][j];
        }
        __syncthreads();
    }
#endif
}

__global__ __launch_bounds__(256) void combine_kernel(float* __restrict__ out)
{
    int i = blockIdx.x * 256 + threadIdx.x;
    if (i >= T * H) return;
    int t = i >> 10;
    int h = i & (H - 1);
    out[i] = g_outpair[(size_t)(2 * t) * H + h] + g_outpair[(size_t)(2 * t + 1) * H + h];
}

// =============== host ===============
typedef CUresult (*PFN_cuTensorMapEncodeTiled)(
    CUtensorMap*, CUtensorMapDataType, cuuint32_t, void*,
    const cuuint64_t*, const cuuint64_t*, const cuuint32_t*, const cuuint32_t*,
    CUtensorMapInterleave, CUtensorMapSwizzle, CUtensorMapL2promotion,
    CUtensorMapFloatOOBfill);

static PFN_cuTensorMapEncodeTiled get_encoder() {
    void* fn = nullptr;
    cudaDriverEntryPointQueryResult st;
    cudaGetDriverEntryPoint("cuTensorMapEncodeTiled", &fn, cudaEnableDefault, &st);
    return (PFN_cuTensorMapEncodeTiled)fn;
}

static void encode_2d(PFN_cuTensorMapEncodeTiled enc, CUtensorMap* tm, void* ptr,
                      uint64_t d0, uint64_t d1, uint32_t b0, uint32_t b1) {
    cuuint64_t dims[2] = {d0, d1};
    cuuint64_t strides[1] = {d0 * 2};   // bf16
    cuuint32_t box[2] = {b0, b1};
    cuuint32_t es[2] = {1, 1};
    enc(tm, CU_TENSOR_MAP_DATA_TYPE_BFLOAT16, 2, ptr, dims, strides, box, es,
        CU_TENSOR_MAP_INTERLEAVE_NONE, CU_TENSOR_MAP_SWIZZLE_128B,
        CU_TENSOR_MAP_L2_PROMOTION_L2_128B, CU_TENSOR_MAP_FLOAT_OOB_FILL_NONE);
}

extern "C" void kernel_launch(void* const* d_in, const int* in_sizes, int n_in,
                              void* d_out, int out_size)
{
    const float* x  = (const float*)d_in[0];
    const float* Wr = (const float*)d_in[1];
    const float* W1 = (const float*)d_in[2];
    const float* W2 = (const float*)d_in[3];
    const float* W3 = (const float*)d_in[4];
    float* out = (float*)d_out;

    __nv_bfloat16 *w1h, *w1l, *w3h, *w3l, *w2h, *w2l, *xgh, *xgl, *hmh, *hml;
    cudaGetSymbolAddress((void**)&w1h, g_w1h);
    cudaGetSymbolAddress((void**)&w1l, g_w1l);
    cudaGetSymbolAddress((void**)&w3h, g_w3h);
    cudaGetSymbolAddress((void**)&w3l, g_w3l);
    cudaGetSymbolAddress((void**)&w2h, g_w2h);
    cudaGetSymbolAddress((void**)&w2l, g_w2l);
    cudaGetSymbolAddress((void**)&xgh, g_xgh);
    cudaGetSymbolAddress((void**)&xgl, g_xgl);
    cudaGetSymbolAddress((void**)&hmh, g_hmh);
    cudaGetSymbolAddress((void**)&hml, g_hml);

    PFN_cuTensorMapEncodeTiled enc = get_encoder();
    CUtensorMap tm_xh, tm_xl, tm_b1h, tm_b1l, tm_b3h, tm_b3l;
    CUtensorMap tm_hh, tm_hl, tm_b2h, tm_b2l;
    if (enc) {
        encode_2d(enc, &tm_xh, xgh, H, SLOTS, BK, 256);           // GEMM1 A: 256 rows
        encode_2d(enc, &tm_xl, xgl, H, SLOTS, BK, 256);
        encode_2d(enc, &tm_b1h, w1h, H, (uint64_t)E * F, BK, BN1);
        encode_2d(enc, &tm_b1l, w1l, H, (uint64_t)E * F, BK, BN1);
        encode_2d(enc, &tm_b3h, w3h, H, (uint64_t)E * F, BK, BN1);
        encode_2d(enc, &tm_b3l, w3l, H, (uint64_t)E * F, BK, BN1);
        encode_2d(enc, &tm_hh, hmh, F, SLOTS, BK, 128);           // GEMM2 A: 128 rows
        encode_2d(enc, &tm_hl, hml, F, SLOTS, BK, 128);
        encode_2d(enc, &tm_b2h, w2h, F, (uint64_t)E * H, BK, BN2); // 256 rows
        encode_2d(enc, &tm_b2l, w2l, F, (uint64_t)E * H, BK, BN2);
    }

    cudaFuncSetAttribute(expert_up_mma,   cudaFuncAttributeMaxDynamicSharedMemorySize, G1_SMEM);
    cudaFuncSetAttribute(expert_down_mma, cudaFuncAttributeMaxDynamicSharedMemorySize, G2_SMEM);

    zero_counts_kernel<<<1, 32>>>();
    router_kernel<<<T, 256>>>(x, Wr);
    finalize_router_kernel<<<1, 1>>>();

    convert_x_kernel<<<(T * H) / (256 * 8), 256>>>(x);
    gather_x_kernel<<<SLOTS, 256>>>();
    {
        dim3 gw13(F / 32, H / 32, E);
        transpose_split_kernel<<<gw13, 256>>>(W1, w1h, w1l, H, F);
        transpose_split_kernel<<<gw13, 256>>>(W3, w3h, w3l, H, F);
        dim3 gw2(H / 32, F / 32, E);
        transpose_split_kernel<<<gw2, 256>>>(W2, w2h, w2l, F, H);
    }

    dim3 g1(F / BN1, MT1, E);
    expert_up_mma<<<g1, 256, G1_SMEM>>>(x, W1, W3, tm_xh, tm_xl,
                                        tm_b1h, tm_b1l, tm_b3h, tm_b3l);

    dim3 g2(H / BN2, MT2, E);
    expert_down_mma<<<g2, 256, G2_SMEM>>>(W2, tm_hh, tm_hl, tm_b2h, tm_b2l);

    combine_kernel<<<(T * H + 255) / 256, 256>>>(out);
}